// round 1
// baseline (speedup 1.0000x reference)
#include <cuda_runtime.h>
#include <math.h>

#define T_SEQ 4096
#define DMODEL 1024
#define NHEADS 16
#define DH 64
#define WIN 256

// Scratch (allocation-free rule: __device__ globals)
__device__ float g_Q[NHEADS * T_SEQ * DH];   // [h][t][d]
__device__ float g_K[NHEADS * T_SEQ * DH];
__device__ float g_V[NHEADS * T_SEQ * DH];
__device__ float g_AO[T_SEQ * DMODEL];       // attention output, [t][h*64+d]

// ---------------------------------------------------------------------------
// GEMM: C[m,n] = sum_k A[m,k] * B[n,k]   (A: MxK row-major, B: NxK row-major)
// M = 4096, N = K = 1024. Tile 128x128x8, 256 threads, 8x8 per thread.
// HEAD_MAJOR: scatter n -> (h = n/64, c = n%64), write C[((h*T)+m)*64 + c].
// ---------------------------------------------------------------------------
template <bool HEAD_MAJOR>
__global__ void gemm_kernel(const float* __restrict__ A,
                            const float* __restrict__ B,
                            float* __restrict__ C) {
    __shared__ float As[8][132];
    __shared__ float Bs[8][132];

    const int bm = blockIdx.y * 128;
    const int bn = blockIdx.x * 128;
    const int tid = threadIdx.x;
    const int ty = tid >> 4;        // 0..15
    const int tx = tid & 15;        // 0..15

    // loader mapping: 128x8 tile, each thread loads one float4 (4 consecutive k)
    const int la_m = (tid * 4) >> 3;   // 0..127
    const int la_k = (tid * 4) & 7;    // 0 or 4

    float acc[8][8];
#pragma unroll
    for (int i = 0; i < 8; i++)
#pragma unroll
        for (int j = 0; j < 8; j++) acc[i][j] = 0.0f;

    const float* Aptr = A + (size_t)(bm + la_m) * DMODEL + la_k;
    const float* Bptr = B + (size_t)(bn + la_m) * DMODEL + la_k;

    for (int k0 = 0; k0 < DMODEL; k0 += 8) {
        float4 a4 = *(const float4*)(Aptr + k0);
        float4 b4 = *(const float4*)(Bptr + k0);
        As[la_k + 0][la_m] = a4.x;
        As[la_k + 1][la_m] = a4.y;
        As[la_k + 2][la_m] = a4.z;
        As[la_k + 3][la_m] = a4.w;
        Bs[la_k + 0][la_m] = b4.x;
        Bs[la_k + 1][la_m] = b4.y;
        Bs[la_k + 2][la_m] = b4.z;
        Bs[la_k + 3][la_m] = b4.w;
        __syncthreads();

#pragma unroll
        for (int kk = 0; kk < 8; kk++) {
            float4 ra0 = *(const float4*)&As[kk][ty * 8];
            float4 ra1 = *(const float4*)&As[kk][ty * 8 + 4];
            float4 rb0 = *(const float4*)&Bs[kk][tx * 8];
            float4 rb1 = *(const float4*)&Bs[kk][tx * 8 + 4];
            float ra[8] = {ra0.x, ra0.y, ra0.z, ra0.w, ra1.x, ra1.y, ra1.z, ra1.w};
            float rb[8] = {rb0.x, rb0.y, rb0.z, rb0.w, rb1.x, rb1.y, rb1.z, rb1.w};
#pragma unroll
            for (int i = 0; i < 8; i++)
#pragma unroll
                for (int j = 0; j < 8; j++)
                    acc[i][j] = fmaf(ra[i], rb[j], acc[i][j]);
        }
        __syncthreads();
    }

#pragma unroll
    for (int i = 0; i < 8; i++) {
        const int m = bm + ty * 8 + i;
#pragma unroll
        for (int j = 0; j < 8; j++) {
            const int n = bn + tx * 8 + j;
            if (HEAD_MAJOR) {
                const int h = n >> 6;
                const int c = n & 63;
                C[((size_t)(h * T_SEQ + m) << 6) + c] = acc[i][j];
            } else {
                C[(size_t)m * DMODEL + n] = acc[i][j];
            }
        }
    }
}

// ---------------------------------------------------------------------------
// Flash-style sliding-window attention.
// One CTA per (64-query tile, head). 256 threads (16x16), 4x4 micro-tile.
// smem: Qs[64][65], KVs[64][65] (K then reused for V), Ss[64][65], row stats.
// ---------------------------------------------------------------------------
#define SROW 65
#define ATTN_SMEM_FLOATS (3 * 64 * SROW + 3 * 64)
#define ATTN_SMEM_BYTES (ATTN_SMEM_FLOATS * 4)

__global__ void attn_kernel() {
    extern __shared__ float sm[];
    float* Qs = sm;                       // 64*65
    float* KVs = Qs + 64 * SROW;          // 64*65 (K, then V)
    float* Ss = KVs + 64 * SROW;          // 64*65
    float* rowM = Ss + 64 * SROW;         // 64
    float* rowL = rowM + 64;              // 64
    float* rowC = rowL + 64;              // 64

    const int q0 = blockIdx.x * 64;
    const int h = blockIdx.y;
    const int tid = threadIdx.x;
    const int ty = tid >> 4;
    const int tx = tid & 15;
    const float scale = 0.125f;           // 1/sqrt(64)

    const float* Qg = g_Q + (size_t)(h * T_SEQ + q0) * DH;
    const float* Kg = g_K + (size_t)h * T_SEQ * DH;
    const float* Vg = g_V + (size_t)h * T_SEQ * DH;

    // Load Q tile (64x64) — 1024 float4s, 4 per thread
#pragma unroll
    for (int u = 0; u < 4; u++) {
        int f = tid + u * 256;            // float4 index
        int r = f >> 4;
        int c4 = f & 15;
        float4 v = *(const float4*)(Qg + r * DH + c4 * 4);
        float* dst = &Qs[r * SROW + c4 * 4];
        dst[0] = v.x; dst[1] = v.y; dst[2] = v.z; dst[3] = v.w;
    }
    if (tid < 64) { rowM[tid] = -1e30f; rowL[tid] = 0.0f; }

    float acc[4][4];
#pragma unroll
    for (int i = 0; i < 4; i++)
#pragma unroll
        for (int j = 0; j < 4; j++) acc[i][j] = 0.0f;

    const int kt_lo = (q0 >= WIN) ? (q0 - WIN) : 0;

    for (int kt = kt_lo; kt <= q0; kt += 64) {
        __syncthreads();   // previous PV done reading KVs / Q ready

        // load K tile
#pragma unroll
        for (int u = 0; u < 4; u++) {
            int f = tid + u * 256;
            int r = f >> 4;
            int c4 = f & 15;
            float4 v = *(const float4*)(Kg + (size_t)(kt + r) * DH + c4 * 4);
            float* dst = &KVs[r * SROW + c4 * 4];
            dst[0] = v.x; dst[1] = v.y; dst[2] = v.z; dst[3] = v.w;
        }
        __syncthreads();

        // S = Q K^T (4x4 per thread)
        float s[4][4];
#pragma unroll
        for (int i = 0; i < 4; i++)
#pragma unroll
            for (int j = 0; j < 4; j++) s[i][j] = 0.0f;
        for (int d = 0; d < DH; d++) {
            float qv[4], kv[4];
#pragma unroll
            for (int i = 0; i < 4; i++) qv[i] = Qs[(ty * 4 + i) * SROW + d];
#pragma unroll
            for (int j = 0; j < 4; j++) kv[j] = KVs[(tx * 4 + j) * SROW + d];
#pragma unroll
            for (int i = 0; i < 4; i++)
#pragma unroll
                for (int j = 0; j < 4; j++)
                    s[i][j] = fmaf(qv[i], kv[j], s[i][j]);
        }
        // mask + scale, write to Ss
#pragma unroll
        for (int i = 0; i < 4; i++) {
            const int gi = q0 + ty * 4 + i;
#pragma unroll
            for (int j = 0; j < 4; j++) {
                const int gj = kt + tx * 4 + j;
                const bool ok = (gj <= gi) && (gj >= gi - WIN);
                Ss[(ty * 4 + i) * SROW + (tx * 4 + j)] = ok ? s[i][j] * scale : -1e30f;
            }
        }
        __syncthreads();

        // load V tile into KVs (K no longer needed)
#pragma unroll
        for (int u = 0; u < 4; u++) {
            int f = tid + u * 256;
            int r = f >> 4;
            int c4 = f & 15;
            float4 v = *(const float4*)(Vg + (size_t)(kt + r) * DH + c4 * 4);
            float* dst = &KVs[r * SROW + c4 * 4];
            dst[0] = v.x; dst[1] = v.y; dst[2] = v.z; dst[3] = v.w;
        }

        // online softmax row update (one thread per row)
        if (tid < 64) {
            const int r = tid;
            float mOld = rowM[r];
            float mx = mOld;
            for (int c = 0; c < 64; c++) mx = fmaxf(mx, Ss[r * SROW + c]);
            float corr = __expf(mOld - mx);
            float sum = 0.0f;
            for (int c = 0; c < 64; c++) {
                float p = __expf(Ss[r * SROW + c] - mx);
                Ss[r * SROW + c] = p;
                sum += p;
            }
            rowM[r] = mx;
            rowL[r] = rowL[r] * corr + sum;
            rowC[r] = corr;
        }
        __syncthreads();

        // acc = acc*corr + P @ V
        float cr[4];
#pragma unroll
        for (int i = 0; i < 4; i++) cr[i] = rowC[ty * 4 + i];
#pragma unroll
        for (int i = 0; i < 4; i++)
#pragma unroll
            for (int j = 0; j < 4; j++) acc[i][j] *= cr[i];
        for (int c = 0; c < 64; c++) {
            float p[4], v[4];
#pragma unroll
            for (int i = 0; i < 4; i++) p[i] = Ss[(ty * 4 + i) * SROW + c];
#pragma unroll
            for (int j = 0; j < 4; j++) v[j] = KVs[c * SROW + tx * 4 + j];
#pragma unroll
            for (int i = 0; i < 4; i++)
#pragma unroll
                for (int j = 0; j < 4; j++)
                    acc[i][j] = fmaf(p[i], v[j], acc[i][j]);
        }
    }

    // epilogue: divide by l, write to g_AO [t][h*64+d]
#pragma unroll
    for (int i = 0; i < 4; i++) {
        const int r = ty * 4 + i;
        const float inv = 1.0f / rowL[r];
#pragma unroll
        for (int j = 0; j < 4; j++) {
            const int d = tx * 4 + j;
            g_AO[(size_t)(q0 + r) * DMODEL + h * DH + d] = acc[i][j] * inv;
        }
    }
}

// ---------------------------------------------------------------------------
extern "C" void kernel_launch(void* const* d_in, const int* in_sizes, int n_in,
                              void* d_out, int out_size) {
    const float* x  = (const float*)d_in[0];
    const float* Wq = (const float*)d_in[1];
    const float* Wk = (const float*)d_in[2];
    const float* Wv = (const float*)d_in[3];
    const float* Wo = (const float*)d_in[4];
    float* out = (float*)d_out;

    float *pQ, *pK, *pV, *pAO;
    cudaGetSymbolAddress((void**)&pQ, g_Q);
    cudaGetSymbolAddress((void**)&pK, g_K);
    cudaGetSymbolAddress((void**)&pV, g_V);
    cudaGetSymbolAddress((void**)&pAO, g_AO);

    dim3 ggrid(DMODEL / 128, T_SEQ / 128);   // (8, 32)
    gemm_kernel<true><<<ggrid, 256>>>(x, Wq, pQ);
    gemm_kernel<true><<<ggrid, 256>>>(x, Wk, pK);
    gemm_kernel<true><<<ggrid, 256>>>(x, Wv, pV);

    static_assert(ATTN_SMEM_BYTES < 64 * 1024, "smem");
    cudaFuncSetAttribute(attn_kernel, cudaFuncAttributeMaxDynamicSharedMemorySize,
                         ATTN_SMEM_BYTES);
    dim3 agrid(T_SEQ / 64, NHEADS);          // (64, 16)
    attn_kernel<<<agrid, 256, ATTN_SMEM_BYTES>>>();

    gemm_kernel<false><<<ggrid, 256>>>(pAO, Wo, out);
}

// round 3
// speedup vs baseline: 1.8932x; 1.8932x over previous
#include <cuda_runtime.h>
#include <cuda_bf16.h>
#include <cstdint>
#include <math.h>

#define T_SEQ 4096
#define DMODEL 1024
#define NHEADS 16
#define DH 64
#define WIN 256

// ---------------------------------------------------------------------------
// Scratch (__device__ globals; allocation-free rule)
// ---------------------------------------------------------------------------
__device__ __align__(16) __nv_bfloat16 g_xh[T_SEQ * DMODEL];
__device__ __align__(16) __nv_bfloat16 g_xl[T_SEQ * DMODEL];
__device__ __align__(16) __nv_bfloat16 g_Wh[4 * DMODEL * DMODEL];
__device__ __align__(16) __nv_bfloat16 g_Wl[4 * DMODEL * DMODEL];
__device__ __align__(16) __nv_bfloat16 g_aoh[T_SEQ * DMODEL];
__device__ __align__(16) __nv_bfloat16 g_aol[T_SEQ * DMODEL];
__device__ float g_Q[NHEADS * T_SEQ * DH];
__device__ float g_K[NHEADS * T_SEQ * DH];
__device__ float g_V[NHEADS * T_SEQ * DH];
__device__ float g_AO[T_SEQ * DMODEL];

// ---------------------------------------------------------------------------
// PTX helpers (generic-PTX only: ldmatrix / mma.sync / cp.async — no tcgen05)
// ---------------------------------------------------------------------------
__device__ __forceinline__ uint32_t smem_u32(const void* p) {
    uint32_t a;
    asm("{ .reg .u64 t; cvta.to.shared.u64 t, %1; cvt.u32.u64 %0, t; }"
        : "=r"(a) : "l"(p));
    return a;
}

__device__ __forceinline__ void cp16(uint32_t dst, const void* src) {
    asm volatile("cp.async.cg.shared.global [%0], [%1], 16;" :: "r"(dst), "l"(src));
}
#define CP_COMMIT() asm volatile("cp.async.commit_group;" ::: "memory")
#define CP_WAIT(n)  asm volatile("cp.async.wait_group %0;" :: "n"(n) : "memory")

__device__ __forceinline__ void ldsm4(uint32_t (&r)[4], uint32_t addr) {
    asm volatile("ldmatrix.sync.aligned.m8n8.x4.shared.b16 {%0,%1,%2,%3}, [%4];"
                 : "=r"(r[0]), "=r"(r[1]), "=r"(r[2]), "=r"(r[3]) : "r"(addr));
}

__device__ __forceinline__ void mma16816(float (&d)[4], const uint32_t (&a)[4],
                                         uint32_t b0, uint32_t b1) {
    asm volatile(
        "mma.sync.aligned.m16n8k16.row.col.f32.bf16.bf16.f32 "
        "{%0,%1,%2,%3}, {%4,%5,%6,%7}, {%8,%9}, {%0,%1,%2,%3};"
        : "+f"(d[0]), "+f"(d[1]), "+f"(d[2]), "+f"(d[3])
        : "r"(a[0]), "r"(a[1]), "r"(a[2]), "r"(a[3]), "r"(b0), "r"(b1));
}

// ---------------------------------------------------------------------------
// fp32 -> (hi, lo) bf16 split
// ---------------------------------------------------------------------------
__global__ void splitk(const float* __restrict__ in,
                       __nv_bfloat16* __restrict__ hi,
                       __nv_bfloat16* __restrict__ lo, int n4) {
    int i = blockIdx.x * 256 + threadIdx.x;
    if (i >= n4) return;
    float4 v = ((const float4*)in)[i];
    float f[4] = {v.x, v.y, v.z, v.w};
    unsigned short h[4], l[4];
#pragma unroll
    for (int j = 0; j < 4; j++) {
        __nv_bfloat16 hb = __float2bfloat16(f[j]);
        __nv_bfloat16 lb = __float2bfloat16(f[j] - __bfloat162float(hb));
        h[j] = __bfloat16_as_ushort(hb);
        l[j] = __bfloat16_as_ushort(lb);
    }
    uint2 uh, ul;
    uh.x = (uint32_t)h[0] | ((uint32_t)h[1] << 16);
    uh.y = (uint32_t)h[2] | ((uint32_t)h[3] << 16);
    ul.x = (uint32_t)l[0] | ((uint32_t)l[1] << 16);
    ul.y = (uint32_t)l[2] | ((uint32_t)l[3] << 16);
    ((uint2*)hi)[i] = uh;
    ((uint2*)lo)[i] = ul;
}

// ---------------------------------------------------------------------------
// Warp-mma split-bf16 GEMM: C[m,n] = sum_k A[m,k]*B[n,k]
// M=4096, N=1024, K=1024. CTA 128x128, 8 warps (warp tile 64x32), KC=32,
// cp.async double-buffered smem, 80B-padded rows (ldmatrix conflict-free).
// ---------------------------------------------------------------------------
#define KC 32
#define ROWB 80
#define TILE_B (128 * ROWB)      // 10240 per tile
#define STAGE_B (4 * TILE_B)     // Ah, Al, Bh, Bl
#define GEMM_SMEM (2 * STAGE_B)  // 81920

__device__ __forceinline__ void gemm_issue(
    uint32_t sb, int stage, int chunk,
    const __nv_bfloat16* __restrict__ Ah, const __nv_bfloat16* __restrict__ Al,
    const __nv_bfloat16* __restrict__ Bh, const __nv_bfloat16* __restrict__ Bl,
    int bm, int bn, int tid) {
    const __nv_bfloat16* gb[4];
    gb[0] = Ah + (size_t)bm * DMODEL;
    gb[1] = Al + (size_t)bm * DMODEL;
    gb[2] = Bh + (size_t)bn * DMODEL;
    gb[3] = Bl + (size_t)bn * DMODEL;
    const uint32_t stbase = sb + (uint32_t)stage * STAGE_B;
#pragma unroll
    for (int arr = 0; arr < 4; arr++) {
#pragma unroll
        for (int i = 0; i < 2; i++) {
            int slot = i * 256 + tid;           // 0..511
            int row = slot >> 2;                // 0..127
            int seg = slot & 3;                 // 0..3 (8 bf16 each)
            uint32_t dst = stbase + (uint32_t)arr * TILE_B + row * ROWB + seg * 16;
            const void* src = gb[arr] + (size_t)row * DMODEL + chunk * KC + seg * 8;
            cp16(dst, src);
        }
    }
    CP_COMMIT();
}

template <bool HEAD_MAJOR>
__global__ void __launch_bounds__(256)
gemm_mma(const __nv_bfloat16* __restrict__ Ah, const __nv_bfloat16* __restrict__ Al,
         const __nv_bfloat16* __restrict__ Bh, const __nv_bfloat16* __restrict__ Bl,
         float* __restrict__ C) {
    extern __shared__ char smraw[];
    const uint32_t sb = smem_u32(smraw);

    const int tid = threadIdx.x;
    const int warp = tid >> 5;
    const int lane = tid & 31;
    const int bm = blockIdx.y * 128;
    const int bn = blockIdx.x * 128;
    const int wm = (warp >> 2) * 64;   // warp M offset (0 or 64)
    const int wn = (warp & 3) * 32;    // warp N offset (0,32,64,96)

    float acc[4][4][4];
#pragma unroll
    for (int i = 0; i < 4; i++)
#pragma unroll
        for (int j = 0; j < 4; j++)
#pragma unroll
            for (int e = 0; e < 4; e++) acc[i][j][e] = 0.0f;

    // ldmatrix lane addressing pieces
    const int lrow = lane & 15;        // row within 16-row block
    const int lseg = lane >> 4;        // k-segment (0/1) within 16-k step

    gemm_issue(sb, 0, 0, Ah, Al, Bh, Bl, bm, bn, tid);

    const int NCH = DMODEL / KC;       // 32
    for (int c = 0; c < NCH; c++) {
        if (c + 1 < NCH) {
            gemm_issue(sb, (c + 1) & 1, c + 1, Ah, Al, Bh, Bl, bm, bn, tid);
            CP_WAIT(1);
        } else {
            CP_WAIT(0);
        }
        __syncthreads();

        const uint32_t st = sb + (uint32_t)(c & 1) * STAGE_B;
#pragma unroll
        for (int kk = 0; kk < 2; kk++) {
            uint32_t a[2][4][4];   // [hi/lo][m-tile][frag]
            uint32_t b[2][2][4];   // [hi/lo][n-half][frag]
#pragma unroll
            for (int t = 0; t < 2; t++)
#pragma unroll
                for (int mi = 0; mi < 4; mi++) {
                    uint32_t addr = st + (uint32_t)t * TILE_B +
                                    (wm + mi * 16 + lrow) * ROWB + kk * 32 + lseg * 16;
                    ldsm4(a[t][mi], addr);
                }
#pragma unroll
            for (int t = 0; t < 2; t++)
#pragma unroll
                for (int nh = 0; nh < 2; nh++) {
                    uint32_t addr = st + (uint32_t)(2 + t) * TILE_B +
                                    (wn + nh * 16 + lrow) * ROWB + kk * 32 + lseg * 16;
                    ldsm4(b[t][nh], addr);
                }
            // 3 terms: (Ah,Bh), (Ah,Bl), (Al,Bh)
#pragma unroll
            for (int mi = 0; mi < 4; mi++)
#pragma unroll
                for (int nj = 0; nj < 4; nj++) {
                    const int nh = nj >> 1, sub = nj & 1;
                    mma16816(acc[mi][nj], a[0][mi], b[0][nh][sub], b[0][nh][sub + 2]);
                    mma16816(acc[mi][nj], a[0][mi], b[1][nh][sub], b[1][nh][sub + 2]);
                    mma16816(acc[mi][nj], a[1][mi], b[0][nh][sub], b[0][nh][sub + 2]);
                }
        }
        __syncthreads();
    }

    // epilogue: direct global stores (float2 per frag half)
    const int r0 = bm + wm + (lane >> 2);
    const int c0 = bn + wn + (lane & 3) * 2;
#pragma unroll
    for (int mi = 0; mi < 4; mi++)
#pragma unroll
        for (int nj = 0; nj < 4; nj++) {
            const int r = r0 + mi * 16;
            const int cc = c0 + nj * 8;
            if (HEAD_MAJOR) {
                const int h = cc >> 6;
                const int cl = cc & 63;
                float* d0 = C + (((size_t)(h * T_SEQ + r)) << 6) + cl;
                float* d1 = C + (((size_t)(h * T_SEQ + r + 8)) << 6) + cl;
                *(float2*)d0 = make_float2(acc[mi][nj][0], acc[mi][nj][1]);
                *(float2*)d1 = make_float2(acc[mi][nj][2], acc[mi][nj][3]);
            } else {
                float* d0 = C + (size_t)r * DMODEL + cc;
                float* d1 = C + (size_t)(r + 8) * DMODEL + cc;
                *(float2*)d0 = make_float2(acc[mi][nj][0], acc[mi][nj][1]);
                *(float2*)d1 = make_float2(acc[mi][nj][2], acc[mi][nj][3]);
            }
        }
}

// ---------------------------------------------------------------------------
// Flash-style sliding-window attention (unchanged from R1 — passed @192us)
// ---------------------------------------------------------------------------
#define SROW 65
#define ATTN_SMEM_FLOATS (3 * 64 * SROW + 3 * 64)
#define ATTN_SMEM_BYTES (ATTN_SMEM_FLOATS * 4)

__global__ void attn_kernel() {
    extern __shared__ float sm[];
    float* Qs = sm;
    float* KVs = Qs + 64 * SROW;
    float* Ss = KVs + 64 * SROW;
    float* rowM = Ss + 64 * SROW;
    float* rowL = rowM + 64;
    float* rowC = rowL + 64;

    const int q0 = blockIdx.x * 64;
    const int h = blockIdx.y;
    const int tid = threadIdx.x;
    const int ty = tid >> 4;
    const int tx = tid & 15;
    const float scale = 0.125f;

    const float* Qg = g_Q + (size_t)(h * T_SEQ + q0) * DH;
    const float* Kg = g_K + (size_t)h * T_SEQ * DH;
    const float* Vg = g_V + (size_t)h * T_SEQ * DH;

#pragma unroll
    for (int u = 0; u < 4; u++) {
        int f = tid + u * 256;
        int r = f >> 4;
        int c4 = f & 15;
        float4 v = *(const float4*)(Qg + r * DH + c4 * 4);
        float* dst = &Qs[r * SROW + c4 * 4];
        dst[0] = v.x; dst[1] = v.y; dst[2] = v.z; dst[3] = v.w;
    }
    if (tid < 64) { rowM[tid] = -1e30f; rowL[tid] = 0.0f; }

    float acc[4][4];
#pragma unroll
    for (int i = 0; i < 4; i++)
#pragma unroll
        for (int j = 0; j < 4; j++) acc[i][j] = 0.0f;

    const int kt_lo = (q0 >= WIN) ? (q0 - WIN) : 0;

    for (int kt = kt_lo; kt <= q0; kt += 64) {
        __syncthreads();
#pragma unroll
        for (int u = 0; u < 4; u++) {
            int f = tid + u * 256;
            int r = f >> 4;
            int c4 = f & 15;
            float4 v = *(const float4*)(Kg + (size_t)(kt + r) * DH + c4 * 4);
            float* dst = &KVs[r * SROW + c4 * 4];
            dst[0] = v.x; dst[1] = v.y; dst[2] = v.z; dst[3] = v.w;
        }
        __syncthreads();

        float s[4][4];
#pragma unroll
        for (int i = 0; i < 4; i++)
#pragma unroll
            for (int j = 0; j < 4; j++) s[i][j] = 0.0f;
        for (int d = 0; d < DH; d++) {
            float qv[4], kv[4];
#pragma unroll
            for (int i = 0; i < 4; i++) qv[i] = Qs[(ty * 4 + i) * SROW + d];
#pragma unroll
            for (int j = 0; j < 4; j++) kv[j] = KVs[(tx * 4 + j) * SROW + d];
#pragma unroll
            for (int i = 0; i < 4; i++)
#pragma unroll
                for (int j = 0; j < 4; j++)
                    s[i][j] = fmaf(qv[i], kv[j], s[i][j]);
        }
#pragma unroll
        for (int i = 0; i < 4; i++) {
            const int gi = q0 + ty * 4 + i;
#pragma unroll
            for (int j = 0; j < 4; j++) {
                const int gj = kt + tx * 4 + j;
                const bool ok = (gj <= gi) && (gj >= gi - WIN);
                Ss[(ty * 4 + i) * SROW + (tx * 4 + j)] = ok ? s[i][j] * scale : -1e30f;
            }
        }
        __syncthreads();

#pragma unroll
        for (int u = 0; u < 4; u++) {
            int f = tid + u * 256;
            int r = f >> 4;
            int c4 = f & 15;
            float4 v = *(const float4*)(Vg + (size_t)(kt + r) * DH + c4 * 4);
            float* dst = &KVs[r * SROW + c4 * 4];
            dst[0] = v.x; dst[1] = v.y; dst[2] = v.z; dst[3] = v.w;
        }

        if (tid < 64) {
            const int r = tid;
            float mOld = rowM[r];
            float mx = mOld;
            for (int c = 0; c < 64; c++) mx = fmaxf(mx, Ss[r * SROW + c]);
            float corr = __expf(mOld - mx);
            float sum = 0.0f;
            for (int c = 0; c < 64; c++) {
                float p = __expf(Ss[r * SROW + c] - mx);
                Ss[r * SROW + c] = p;
                sum += p;
            }
            rowM[r] = mx;
            rowL[r] = rowL[r] * corr + sum;
            rowC[r] = corr;
        }
        __syncthreads();

        float cr[4];
#pragma unroll
        for (int i = 0; i < 4; i++) cr[i] = rowC[ty * 4 + i];
#pragma unroll
        for (int i = 0; i < 4; i++)
#pragma unroll
            for (int j = 0; j < 4; j++) acc[i][j] *= cr[i];
        for (int c = 0; c < 64; c++) {
            float p[4], v[4];
#pragma unroll
            for (int i = 0; i < 4; i++) p[i] = Ss[(ty * 4 + i) * SROW + c];
#pragma unroll
            for (int j = 0; j < 4; j++) v[j] = KVs[c * SROW + tx * 4 + j];
#pragma unroll
            for (int i = 0; i < 4; i++)
#pragma unroll
                for (int j = 0; j < 4; j++)
                    acc[i][j] = fmaf(p[i], v[j], acc[i][j]);
        }
    }

#pragma unroll
    for (int i = 0; i < 4; i++) {
        const int r = ty * 4 + i;
        const float inv = 1.0f / rowL[r];
#pragma unroll
        for (int j = 0; j < 4; j++) {
            const int d = tx * 4 + j;
            g_AO[(size_t)(q0 + r) * DMODEL + h * DH + d] = acc[i][j] * inv;
        }
    }
}

// ---------------------------------------------------------------------------
extern "C" void kernel_launch(void* const* d_in, const int* in_sizes, int n_in,
                              void* d_out, int out_size) {
    const float* x  = (const float*)d_in[0];
    const float* Wq = (const float*)d_in[1];
    const float* Wk = (const float*)d_in[2];
    const float* Wv = (const float*)d_in[3];
    const float* Wo = (const float*)d_in[4];
    float* out = (float*)d_out;

    float *pQ, *pK, *pV, *pAO;
    __nv_bfloat16 *pxh, *pxl, *pWh, *pWl, *paoh, *paol;
    cudaGetSymbolAddress((void**)&pQ, g_Q);
    cudaGetSymbolAddress((void**)&pK, g_K);
    cudaGetSymbolAddress((void**)&pV, g_V);
    cudaGetSymbolAddress((void**)&pAO, g_AO);
    cudaGetSymbolAddress((void**)&pxh, g_xh);
    cudaGetSymbolAddress((void**)&pxl, g_xl);
    cudaGetSymbolAddress((void**)&pWh, g_Wh);
    cudaGetSymbolAddress((void**)&pWl, g_Wl);
    cudaGetSymbolAddress((void**)&paoh, g_aoh);
    cudaGetSymbolAddress((void**)&paol, g_aol);

    cudaFuncSetAttribute(gemm_mma<true>, cudaFuncAttributeMaxDynamicSharedMemorySize,
                         GEMM_SMEM);
    cudaFuncSetAttribute(gemm_mma<false>, cudaFuncAttributeMaxDynamicSharedMemorySize,
                         GEMM_SMEM);
    cudaFuncSetAttribute(attn_kernel, cudaFuncAttributeMaxDynamicSharedMemorySize,
                         ATTN_SMEM_BYTES);

    const int n4x = T_SEQ * DMODEL / 4;
    const int n4w = DMODEL * DMODEL / 4;
    const int WSZ = DMODEL * DMODEL;

    splitk<<<n4x / 256, 256>>>(x, pxh, pxl, n4x);
    splitk<<<n4w / 256, 256>>>(Wq, pWh + 0 * WSZ, pWl + 0 * WSZ, n4w);
    splitk<<<n4w / 256, 256>>>(Wk, pWh + 1 * WSZ, pWl + 1 * WSZ, n4w);
    splitk<<<n4w / 256, 256>>>(Wv, pWh + 2 * WSZ, pWl + 2 * WSZ, n4w);
    splitk<<<n4w / 256, 256>>>(Wo, pWh + 3 * WSZ, pWl + 3 * WSZ, n4w);

    dim3 ggrid(DMODEL / 128, T_SEQ / 128);  // (8, 32)
    gemm_mma<true><<<ggrid, 256, GEMM_SMEM>>>(pxh, pxl, pWh + 0 * WSZ, pWl + 0 * WSZ, pQ);
    gemm_mma<true><<<ggrid, 256, GEMM_SMEM>>>(pxh, pxl, pWh + 1 * WSZ, pWl + 1 * WSZ, pK);
    gemm_mma<true><<<ggrid, 256, GEMM_SMEM>>>(pxh, pxl, pWh + 2 * WSZ, pWl + 2 * WSZ, pV);

    dim3 agrid(T_SEQ / 64, NHEADS);
    attn_kernel<<<agrid, 256, ATTN_SMEM_BYTES>>>();

    splitk<<<n4x / 256, 256>>>(pAO, paoh, paol, n4x);
    gemm_mma<false><<<ggrid, 256, GEMM_SMEM>>>(paoh, paol, pWh + 3 * WSZ, pWl + 3 * WSZ, out);
}

// round 4
// speedup vs baseline: 2.2896x; 1.2094x over previous
#include <cuda_runtime.h>
#include <cuda_bf16.h>
#include <cstdint>
#include <math.h>

#define T_SEQ 4096
#define DMODEL 1024
#define NHEADS 16
#define DH 64
#define WIN 256

// ---------------------------------------------------------------------------
// Scratch (__device__ globals; allocation-free rule)
// ---------------------------------------------------------------------------
__device__ __align__(16) __nv_bfloat16 g_xh[T_SEQ * DMODEL];
__device__ __align__(16) __nv_bfloat16 g_xl[T_SEQ * DMODEL];
__device__ __align__(16) __nv_bfloat16 g_Wh[4 * DMODEL * DMODEL];
__device__ __align__(16) __nv_bfloat16 g_Wl[4 * DMODEL * DMODEL];
__device__ __align__(16) __nv_bfloat16 g_aoh[T_SEQ * DMODEL];
__device__ __align__(16) __nv_bfloat16 g_aol[T_SEQ * DMODEL];
// Q/K head-major [h][t][d], V transposed [h][d][t]; all bf16 hi/lo
__device__ __align__(16) __nv_bfloat16 g_Qh[NHEADS * T_SEQ * DH];
__device__ __align__(16) __nv_bfloat16 g_Ql[NHEADS * T_SEQ * DH];
__device__ __align__(16) __nv_bfloat16 g_Kh[NHEADS * T_SEQ * DH];
__device__ __align__(16) __nv_bfloat16 g_Kl[NHEADS * T_SEQ * DH];
__device__ __align__(16) __nv_bfloat16 g_Vth[NHEADS * DH * T_SEQ];
__device__ __align__(16) __nv_bfloat16 g_Vtl[NHEADS * DH * T_SEQ];

// ---------------------------------------------------------------------------
// PTX helpers (generic PTX only — no tcgen05 on compute_103 virtual arch)
// ---------------------------------------------------------------------------
__device__ __forceinline__ uint32_t smem_u32(const void* p) {
    uint32_t a;
    asm("{ .reg .u64 t; cvta.to.shared.u64 t, %1; cvt.u32.u64 %0, t; }"
        : "=r"(a) : "l"(p));
    return a;
}

__device__ __forceinline__ void cp16(uint32_t dst, const void* src) {
    asm volatile("cp.async.cg.shared.global [%0], [%1], 16;" :: "r"(dst), "l"(src));
}
#define CP_COMMIT() asm volatile("cp.async.commit_group;" ::: "memory")
#define CP_WAIT(n)  asm volatile("cp.async.wait_group %0;" :: "n"(n) : "memory")

__device__ __forceinline__ void ldsm4(uint32_t (&r)[4], uint32_t addr) {
    asm volatile("ldmatrix.sync.aligned.m8n8.x4.shared.b16 {%0,%1,%2,%3}, [%4];"
                 : "=r"(r[0]), "=r"(r[1]), "=r"(r[2]), "=r"(r[3]) : "r"(addr));
}

__device__ __forceinline__ void mma16816(float (&d)[4], const uint32_t (&a)[4],
                                         uint32_t b0, uint32_t b1) {
    asm volatile(
        "mma.sync.aligned.m16n8k16.row.col.f32.bf16.bf16.f32 "
        "{%0,%1,%2,%3}, {%4,%5,%6,%7}, {%8,%9}, {%0,%1,%2,%3};"
        : "+f"(d[0]), "+f"(d[1]), "+f"(d[2]), "+f"(d[3])
        : "r"(a[0]), "r"(a[1]), "r"(a[2]), "r"(a[3]), "r"(b0), "r"(b1));
}

__device__ __forceinline__ uint32_t packbf(float x, float y) {
    unsigned short lx = __bfloat16_as_ushort(__float2bfloat16(x));
    unsigned short ly = __bfloat16_as_ushort(__float2bfloat16(y));
    return (uint32_t)lx | ((uint32_t)ly << 16);
}

// ---------------------------------------------------------------------------
// fp32 -> (hi, lo) bf16 split (x and W inputs)
// ---------------------------------------------------------------------------
__global__ void splitk(const float* __restrict__ in,
                       __nv_bfloat16* __restrict__ hi,
                       __nv_bfloat16* __restrict__ lo, int n4) {
    int i = blockIdx.x * 256 + threadIdx.x;
    if (i >= n4) return;
    float4 v = ((const float4*)in)[i];
    float f[4] = {v.x, v.y, v.z, v.w};
    unsigned short h[4], l[4];
#pragma unroll
    for (int j = 0; j < 4; j++) {
        __nv_bfloat16 hb = __float2bfloat16(f[j]);
        __nv_bfloat16 lb = __float2bfloat16(f[j] - __bfloat162float(hb));
        h[j] = __bfloat16_as_ushort(hb);
        l[j] = __bfloat16_as_ushort(lb);
    }
    uint2 uh, ul;
    uh.x = (uint32_t)h[0] | ((uint32_t)h[1] << 16);
    uh.y = (uint32_t)h[2] | ((uint32_t)h[3] << 16);
    ul.x = (uint32_t)l[0] | ((uint32_t)l[1] << 16);
    ul.y = (uint32_t)l[2] | ((uint32_t)l[3] << 16);
    ((uint2*)hi)[i] = uh;
    ((uint2*)lo)[i] = ul;
}

// ---------------------------------------------------------------------------
// Warp-mma split-bf16 GEMM (mainloop identical to R3; epilogue variants)
// EPI 0: fp32 row-major.  EPI 1: bf16 hi/lo head-major [h][t][d] (*scale).
// EPI 2: bf16 hi/lo transposed [h][d][t] via smem staging.
// ---------------------------------------------------------------------------
#define KC 32
#define ROWB 80
#define TILE_B (128 * ROWB)
#define STAGE_B (4 * TILE_B)
#define GEMM_SMEM (2 * STAGE_B)  // 81920

__device__ __forceinline__ void gemm_issue(
    uint32_t sb, int stage, int chunk,
    const __nv_bfloat16* __restrict__ Ah, const __nv_bfloat16* __restrict__ Al,
    const __nv_bfloat16* __restrict__ Bh, const __nv_bfloat16* __restrict__ Bl,
    int bm, int bn, int tid) {
    const __nv_bfloat16* gb[4];
    gb[0] = Ah + (size_t)bm * DMODEL;
    gb[1] = Al + (size_t)bm * DMODEL;
    gb[2] = Bh + (size_t)bn * DMODEL;
    gb[3] = Bl + (size_t)bn * DMODEL;
    const uint32_t stbase = sb + (uint32_t)stage * STAGE_B;
#pragma unroll
    for (int arr = 0; arr < 4; arr++) {
#pragma unroll
        for (int i = 0; i < 2; i++) {
            int slot = i * 256 + tid;
            int row = slot >> 2;
            int seg = slot & 3;
            uint32_t dst = stbase + (uint32_t)arr * TILE_B + row * ROWB + seg * 16;
            const void* src = gb[arr] + (size_t)row * DMODEL + chunk * KC + seg * 8;
            cp16(dst, src);
        }
    }
    CP_COMMIT();
}

template <int EPI>
__global__ void __launch_bounds__(256)
gemm_mma(const __nv_bfloat16* __restrict__ Ah, const __nv_bfloat16* __restrict__ Al,
         const __nv_bfloat16* __restrict__ Bh, const __nv_bfloat16* __restrict__ Bl,
         float* __restrict__ Cf, __nv_bfloat16* __restrict__ Ch,
         __nv_bfloat16* __restrict__ Cl, float scale) {
    extern __shared__ char smraw[];
    const uint32_t sb = smem_u32(smraw);

    const int tid = threadIdx.x;
    const int warp = tid >> 5;
    const int lane = tid & 31;
    const int bm = blockIdx.y * 128;
    const int bn = blockIdx.x * 128;
    const int wm = (warp >> 2) * 64;
    const int wn = (warp & 3) * 32;

    float acc[4][4][4];
#pragma unroll
    for (int i = 0; i < 4; i++)
#pragma unroll
        for (int j = 0; j < 4; j++)
#pragma unroll
            for (int e = 0; e < 4; e++) acc[i][j][e] = 0.0f;

    const int lrow = lane & 15;
    const int lseg = lane >> 4;

    gemm_issue(sb, 0, 0, Ah, Al, Bh, Bl, bm, bn, tid);

    const int NCH = DMODEL / KC;
    for (int c = 0; c < NCH; c++) {
        if (c + 1 < NCH) {
            gemm_issue(sb, (c + 1) & 1, c + 1, Ah, Al, Bh, Bl, bm, bn, tid);
            CP_WAIT(1);
        } else {
            CP_WAIT(0);
        }
        __syncthreads();

        const uint32_t st = sb + (uint32_t)(c & 1) * STAGE_B;
#pragma unroll
        for (int kk = 0; kk < 2; kk++) {
            uint32_t a[2][4][4];
            uint32_t b[2][2][4];
#pragma unroll
            for (int t = 0; t < 2; t++)
#pragma unroll
                for (int mi = 0; mi < 4; mi++) {
                    uint32_t addr = st + (uint32_t)t * TILE_B +
                                    (wm + mi * 16 + lrow) * ROWB + kk * 32 + lseg * 16;
                    ldsm4(a[t][mi], addr);
                }
#pragma unroll
            for (int t = 0; t < 2; t++)
#pragma unroll
                for (int nh = 0; nh < 2; nh++) {
                    uint32_t addr = st + (uint32_t)(2 + t) * TILE_B +
                                    (wn + nh * 16 + lrow) * ROWB + kk * 32 + lseg * 16;
                    ldsm4(b[t][nh], addr);
                }
#pragma unroll
            for (int mi = 0; mi < 4; mi++)
#pragma unroll
                for (int nj = 0; nj < 4; nj++) {
                    const int nh = nj >> 1, sub = nj & 1;
                    mma16816(acc[mi][nj], a[0][mi], b[0][nh][sub], b[0][nh][sub + 2]);
                    mma16816(acc[mi][nj], a[0][mi], b[1][nh][sub], b[1][nh][sub + 2]);
                    mma16816(acc[mi][nj], a[1][mi], b[0][nh][sub], b[0][nh][sub + 2]);
                }
        }
        __syncthreads();
    }

    if (EPI == 0) {
        const int r0 = bm + wm + (lane >> 2);
        const int c0 = bn + wn + (lane & 3) * 2;
#pragma unroll
        for (int mi = 0; mi < 4; mi++)
#pragma unroll
            for (int nj = 0; nj < 4; nj++) {
                const int r = r0 + mi * 16;
                const int cc = c0 + nj * 8;
                float* d0 = Cf + (size_t)r * DMODEL + cc;
                float* d1 = Cf + (size_t)(r + 8) * DMODEL + cc;
                *(float2*)d0 = make_float2(acc[mi][nj][0], acc[mi][nj][1]);
                *(float2*)d1 = make_float2(acc[mi][nj][2], acc[mi][nj][3]);
            }
    } else if (EPI == 1) {
        const int r0 = bm + wm + (lane >> 2);
        const int c0 = bn + wn + (lane & 3) * 2;
#pragma unroll
        for (int mi = 0; mi < 4; mi++)
#pragma unroll
            for (int nj = 0; nj < 4; nj++) {
                const int r = r0 + mi * 16;
                const int cc = c0 + nj * 8;
                const int h = cc >> 6;
                const int cl = cc & 63;
#pragma unroll
                for (int half = 0; half < 2; half++) {
                    float v0 = acc[mi][nj][half * 2 + 0] * scale;
                    float v1 = acc[mi][nj][half * 2 + 1] * scale;
                    __nv_bfloat16 h0 = __float2bfloat16(v0);
                    __nv_bfloat16 h1 = __float2bfloat16(v1);
                    float l0 = v0 - __bfloat162float(h0);
                    float l1 = v1 - __bfloat162float(h1);
                    size_t base = ((size_t)(h * T_SEQ + r + half * 8) << 6) + cl;
                    *(uint32_t*)(Ch + base) =
                        (uint32_t)__bfloat16_as_ushort(h0) |
                        ((uint32_t)__bfloat16_as_ushort(h1) << 16);
                    *(uint32_t*)(Cl + base) = packbf(l0, l1);
                }
            }
    } else {
        // EPI 2: transpose via smem staging (reuse pipeline buffers)
        __nv_bfloat16* sVh = (__nv_bfloat16*)smraw;
        __nv_bfloat16* sVl = sVh + 128 * 136;
        const int lr0 = wm + (lane >> 2);
        const int lc0 = wn + (lane & 3) * 2;
#pragma unroll
        for (int mi = 0; mi < 4; mi++)
#pragma unroll
            for (int nj = 0; nj < 4; nj++) {
                const int lr = lr0 + mi * 16;
                const int lc = lc0 + nj * 8;
#pragma unroll
                for (int half = 0; half < 2; half++) {
                    float v0 = acc[mi][nj][half * 2 + 0];
                    float v1 = acc[mi][nj][half * 2 + 1];
                    __nv_bfloat16 h0 = __float2bfloat16(v0);
                    __nv_bfloat16 h1 = __float2bfloat16(v1);
                    int rr = lr + half * 8;
                    sVh[lc * 136 + rr] = h0;
                    sVh[(lc + 1) * 136 + rr] = h1;
                    sVl[lc * 136 + rr] = __float2bfloat16(v0 - __bfloat162float(h0));
                    sVl[(lc + 1) * 136 + rr] = __float2bfloat16(v1 - __bfloat162float(h1));
                }
            }
        __syncthreads();
        for (int i = tid; i < 128 * 16; i += 256) {
            int row = i >> 4, seg = i & 15;
            int gn = bn + row;
            int hh = gn >> 6, dd = gn & 63;
            size_t dst = (size_t)(hh * DH + dd) * T_SEQ + bm + seg * 8;
            *(uint4*)(Ch + dst) = *(uint4*)(sVh + row * 136 + seg * 8);
            *(uint4*)(Cl + dst) = *(uint4*)(sVl + row * 136 + seg * 8);
        }
    }
}

// ---------------------------------------------------------------------------
// HMMA sliding-window attention. CTA = (64-query tile, head), 4 warps.
// K tiles [key][d], Vt tiles [d][key]; rows padded to 176B (ldmatrix clean).
// 3-term split for both QK^T and PV. Epilogue writes bf16 hi/lo AO.
// ---------------------------------------------------------------------------
#define AROWB 176
#define ATILE (64 * AROWB)        // 11264
#define ASTAGE (4 * ATILE)        // 45056
#define ATTN_SMEM (2 * ASTAGE)    // 90112
#define OFF_KH 0
#define OFF_KL ATILE
#define OFF_VH (2 * ATILE)
#define OFF_VL (3 * ATILE)

__device__ __forceinline__ void attn_load_tile(
    uint32_t base, const __nv_bfloat16* __restrict__ Kh,
    const __nv_bfloat16* __restrict__ Kl,
    const __nv_bfloat16* __restrict__ Vth,
    const __nv_bfloat16* __restrict__ Vtl,
    int h, int kt, int tid) {
#pragma unroll
    for (int i = 0; i < 4; i++) {
        int idx = tid + i * 128;
        int row = idx >> 3, seg = idx & 7;
        uint32_t dk = base + OFF_KH + row * AROWB + seg * 16;
        size_t ks = ((size_t)(h * T_SEQ + kt + row) << 6) + seg * 8;
        cp16(dk, Kh + ks);
        cp16(dk + ATILE, Kl + ks);
        uint32_t dv = base + OFF_VH + row * AROWB + seg * 16;
        size_t vs = (size_t)(h * DH + row) * T_SEQ + kt + seg * 8;
        cp16(dv, Vth + vs);
        cp16(dv + ATILE, Vtl + vs);
    }
    CP_COMMIT();
}

__global__ void __launch_bounds__(128)
attn_mma(const __nv_bfloat16* __restrict__ Qh, const __nv_bfloat16* __restrict__ Ql,
         const __nv_bfloat16* __restrict__ Kh, const __nv_bfloat16* __restrict__ Kl,
         const __nv_bfloat16* __restrict__ Vth, const __nv_bfloat16* __restrict__ Vtl,
         __nv_bfloat16* __restrict__ AOh, __nv_bfloat16* __restrict__ AOl) {
    extern __shared__ char smraw[];
    const uint32_t sb = smem_u32(smraw);
    const int tid = threadIdx.x;
    const int warp = tid >> 5;
    const int lane = tid & 31;
    const int h = blockIdx.y;
    const int q0 = blockIdx.x * 64;
    const int lrow = lane & 15;
    const int lseg = lane >> 4;

    // stage Q (pre-scaled by 1/8 in the Q-GEMM epilogue) into stage0 K slots
#pragma unroll
    for (int i = 0; i < 4; i++) {
        int idx = tid + i * 128;
        int row = idx >> 3, seg = idx & 7;
        uint32_t dst = sb + OFF_KH + row * AROWB + seg * 16;
        size_t qs = ((size_t)(h * T_SEQ + q0 + row) << 6) + seg * 8;
        cp16(dst, Qh + qs);
        cp16(dst + ATILE, Ql + qs);
    }
    CP_COMMIT();
    CP_WAIT(0);
    __syncthreads();

    uint32_t qfh[4][4], qfl[4][4];
#pragma unroll
    for (int k = 0; k < 4; k++) {
        uint32_t ad = sb + (warp * 16 + lrow) * AROWB + k * 32 + lseg * 16;
        ldsm4(qfh[k], ad);
        ldsm4(qfl[k], ad + ATILE);
    }
    __syncthreads();

    float o[8][4];
#pragma unroll
    for (int j = 0; j < 8; j++)
#pragma unroll
        for (int e = 0; e < 4; e++) o[j][e] = 0.0f;
    float m0 = -1e30f, m1 = -1e30f, l0 = 0.0f, l1 = 0.0f;

    const int kt_lo = (q0 >= WIN) ? (q0 - WIN) : 0;
    const int ntiles = (q0 - kt_lo) / 64 + 1;

    attn_load_tile(sb, Kh, Kl, Vth, Vtl, h, kt_lo, tid);
    if (ntiles > 1) attn_load_tile(sb + ASTAGE, Kh, Kl, Vth, Vtl, h, kt_lo + 64, tid);

    for (int ti = 0; ti < ntiles; ti++) {
        const int kt = kt_lo + ti * 64;
        const uint32_t base = sb + (uint32_t)(ti & 1) * ASTAGE;
        if (ti + 1 < ntiles) { CP_WAIT(1); } else { CP_WAIT(0); }
        __syncthreads();

        // ---- S = Q K^T (3-term) ----
        float sf[8][4];
#pragma unroll
        for (int j = 0; j < 8; j++)
#pragma unroll
            for (int e = 0; e < 4; e++) sf[j][e] = 0.0f;
#pragma unroll
        for (int kk = 0; kk < 4; kk++) {
            uint32_t bh[4][4], bl[4][4];
#pragma unroll
            for (int n16 = 0; n16 < 4; n16++) {
                uint32_t ad = base + OFF_KH + (n16 * 16 + lrow) * AROWB + kk * 32 + lseg * 16;
                ldsm4(bh[n16], ad);
                ldsm4(bl[n16], ad + ATILE);
            }
#pragma unroll
            for (int j = 0; j < 8; j++) {
                const int nh = j >> 1, sub = j & 1;
                mma16816(sf[j], qfh[kk], bh[nh][sub], bh[nh][sub + 2]);
                mma16816(sf[j], qfh[kk], bl[nh][sub], bl[nh][sub + 2]);
                mma16816(sf[j], qfl[kk], bh[nh][sub], bh[nh][sub + 2]);
            }
        }

        // ---- mask ----
        const int r0 = q0 + warp * 16 + (lane >> 2);
        const int r1 = r0 + 8;
#pragma unroll
        for (int j = 0; j < 8; j++) {
            const int c0 = kt + 8 * j + (lane & 3) * 2;
            const int c1 = c0 + 1;
            if (c0 > r0 || c0 < r0 - WIN) sf[j][0] = -1e30f;
            if (c1 > r0 || c1 < r0 - WIN) sf[j][1] = -1e30f;
            if (c0 > r1 || c0 < r1 - WIN) sf[j][2] = -1e30f;
            if (c1 > r1 || c1 < r1 - WIN) sf[j][3] = -1e30f;
        }

        // ---- online softmax (rows warp-local; quad shuffle over cols) ----
        float t0 = -1e30f, t1 = -1e30f;
#pragma unroll
        for (int j = 0; j < 8; j++) {
            t0 = fmaxf(t0, fmaxf(sf[j][0], sf[j][1]));
            t1 = fmaxf(t1, fmaxf(sf[j][2], sf[j][3]));
        }
        t0 = fmaxf(t0, __shfl_xor_sync(0xffffffffu, t0, 1));
        t0 = fmaxf(t0, __shfl_xor_sync(0xffffffffu, t0, 2));
        t1 = fmaxf(t1, __shfl_xor_sync(0xffffffffu, t1, 1));
        t1 = fmaxf(t1, __shfl_xor_sync(0xffffffffu, t1, 2));
        const float mn0 = fmaxf(m0, t0), mn1 = fmaxf(m1, t1);
        const float corr0 = __expf(m0 - mn0), corr1 = __expf(m1 - mn1);
        m0 = mn0;
        m1 = mn1;

        uint32_t ph[4][4], pl[4][4];
        float s0 = 0.0f, s1 = 0.0f;
#pragma unroll
        for (int j = 0; j < 8; j++) {
            float p0 = __expf(sf[j][0] - m0);
            float p1 = __expf(sf[j][1] - m0);
            float p2 = __expf(sf[j][2] - m1);
            float p3 = __expf(sf[j][3] - m1);
            s0 += p0 + p1;
            s1 += p2 + p3;
            __nv_bfloat16 b0 = __float2bfloat16(p0), b1 = __float2bfloat16(p1);
            __nv_bfloat16 b2 = __float2bfloat16(p2), b3 = __float2bfloat16(p3);
            const int kk = j >> 1, pos = (j & 1) * 2;
            ph[kk][pos + 0] = (uint32_t)__bfloat16_as_ushort(b0) |
                              ((uint32_t)__bfloat16_as_ushort(b1) << 16);
            ph[kk][pos + 1] = (uint32_t)__bfloat16_as_ushort(b2) |
                              ((uint32_t)__bfloat16_as_ushort(b3) << 16);
            pl[kk][pos + 0] = packbf(p0 - __bfloat162float(b0), p1 - __bfloat162float(b1));
            pl[kk][pos + 1] = packbf(p2 - __bfloat162float(b2), p3 - __bfloat162float(b3));
        }
        s0 += __shfl_xor_sync(0xffffffffu, s0, 1);
        s0 += __shfl_xor_sync(0xffffffffu, s0, 2);
        s1 += __shfl_xor_sync(0xffffffffu, s1, 1);
        s1 += __shfl_xor_sync(0xffffffffu, s1, 2);
        l0 = l0 * corr0 + s0;
        l1 = l1 * corr1 + s1;
#pragma unroll
        for (int j = 0; j < 8; j++) {
            o[j][0] *= corr0;
            o[j][1] *= corr0;
            o[j][2] *= corr1;
            o[j][3] *= corr1;
        }

        // ---- O += P V (3-term) ----
#pragma unroll
        for (int kk = 0; kk < 4; kk++) {
            uint32_t vh[4][4], vl[4][4];
#pragma unroll
            for (int n16 = 0; n16 < 4; n16++) {
                uint32_t ad = base + OFF_VH + (n16 * 16 + lrow) * AROWB + kk * 32 + lseg * 16;
                ldsm4(vh[n16], ad);
                ldsm4(vl[n16], ad + ATILE);
            }
#pragma unroll
            for (int j = 0; j < 8; j++) {
                const int nh = j >> 1, sub = j & 1;
                mma16816(o[j], ph[kk], vh[nh][sub], vh[nh][sub + 2]);
                mma16816(o[j], ph[kk], vl[nh][sub], vl[nh][sub + 2]);
                mma16816(o[j], pl[kk], vh[nh][sub], vh[nh][sub + 2]);
            }
        }
        __syncthreads();
        if (ti + 2 < ntiles)
            attn_load_tile(sb + (uint32_t)(ti & 1) * ASTAGE, Kh, Kl, Vth, Vtl, h,
                           kt + 128, tid);
    }

    // ---- epilogue: O/l -> bf16 hi/lo AO [t][h*64+d] ----
    const float i0 = 1.0f / l0;
    const float i1 = 1.0f / l1;
    const int tr = q0 + warp * 16 + (lane >> 2);
#pragma unroll
    for (int j = 0; j < 8; j++) {
        const int d = 8 * j + (lane & 3) * 2;
        float v0 = o[j][0] * i0, v1 = o[j][1] * i0;
        float v2 = o[j][2] * i1, v3 = o[j][3] * i1;
        __nv_bfloat16 h0 = __float2bfloat16(v0), h1 = __float2bfloat16(v1);
        __nv_bfloat16 h2 = __float2bfloat16(v2), h3 = __float2bfloat16(v3);
        size_t a0 = (size_t)tr * DMODEL + h * DH + d;
        size_t a1 = (size_t)(tr + 8) * DMODEL + h * DH + d;
        *(uint32_t*)(AOh + a0) = (uint32_t)__bfloat16_as_ushort(h0) |
                                 ((uint32_t)__bfloat16_as_ushort(h1) << 16);
        *(uint32_t*)(AOh + a1) = (uint32_t)__bfloat16_as_ushort(h2) |
                                 ((uint32_t)__bfloat16_as_ushort(h3) << 16);
        *(uint32_t*)(AOl + a0) = packbf(v0 - __bfloat162float(h0), v1 - __bfloat162float(h1));
        *(uint32_t*)(AOl + a1) = packbf(v2 - __bfloat162float(h2), v3 - __bfloat162float(h3));
    }
}

// ---------------------------------------------------------------------------
extern "C" void kernel_launch(void* const* d_in, const int* in_sizes, int n_in,
                              void* d_out, int out_size) {
    const float* x  = (const float*)d_in[0];
    const float* Wq = (const float*)d_in[1];
    const float* Wk = (const float*)d_in[2];
    const float* Wv = (const float*)d_in[3];
    const float* Wo = (const float*)d_in[4];
    float* out = (float*)d_out;

    __nv_bfloat16 *pxh, *pxl, *pWh, *pWl, *paoh, *paol;
    __nv_bfloat16 *pQh, *pQl, *pKh, *pKl, *pVth, *pVtl;
    cudaGetSymbolAddress((void**)&pxh, g_xh);
    cudaGetSymbolAddress((void**)&pxl, g_xl);
    cudaGetSymbolAddress((void**)&pWh, g_Wh);
    cudaGetSymbolAddress((void**)&pWl, g_Wl);
    cudaGetSymbolAddress((void**)&paoh, g_aoh);
    cudaGetSymbolAddress((void**)&paol, g_aol);
    cudaGetSymbolAddress((void**)&pQh, g_Qh);
    cudaGetSymbolAddress((void**)&pQl, g_Ql);
    cudaGetSymbolAddress((void**)&pKh, g_Kh);
    cudaGetSymbolAddress((void**)&pKl, g_Kl);
    cudaGetSymbolAddress((void**)&pVth, g_Vth);
    cudaGetSymbolAddress((void**)&pVtl, g_Vtl);

    cudaFuncSetAttribute(gemm_mma<0>, cudaFuncAttributeMaxDynamicSharedMemorySize, GEMM_SMEM);
    cudaFuncSetAttribute(gemm_mma<1>, cudaFuncAttributeMaxDynamicSharedMemorySize, GEMM_SMEM);
    cudaFuncSetAttribute(gemm_mma<2>, cudaFuncAttributeMaxDynamicSharedMemorySize, GEMM_SMEM);
    cudaFuncSetAttribute(attn_mma, cudaFuncAttributeMaxDynamicSharedMemorySize, ATTN_SMEM);

    const int n4x = T_SEQ * DMODEL / 4;
    const int n4w = DMODEL * DMODEL / 4;
    const int WSZ = DMODEL * DMODEL;

    splitk<<<n4x / 256, 256>>>(x, pxh, pxl, n4x);
    splitk<<<n4w / 256, 256>>>(Wq, pWh + 0 * WSZ, pWl + 0 * WSZ, n4w);
    splitk<<<n4w / 256, 256>>>(Wk, pWh + 1 * WSZ, pWl + 1 * WSZ, n4w);
    splitk<<<n4w / 256, 256>>>(Wv, pWh + 2 * WSZ, pWl + 2 * WSZ, n4w);
    splitk<<<n4w / 256, 256>>>(Wo, pWh + 3 * WSZ, pWl + 3 * WSZ, n4w);

    dim3 ggrid(DMODEL / 128, T_SEQ / 128);  // (8, 32)
    // Q: pre-scale by 1/sqrt(DH) = 0.125
    gemm_mma<1><<<ggrid, 256, GEMM_SMEM>>>(pxh, pxl, pWh + 0 * WSZ, pWl + 0 * WSZ,
                                           nullptr, pQh, pQl, 0.125f);
    gemm_mma<1><<<ggrid, 256, GEMM_SMEM>>>(pxh, pxl, pWh + 1 * WSZ, pWl + 1 * WSZ,
                                           nullptr, pKh, pKl, 1.0f);
    gemm_mma<2><<<ggrid, 256, GEMM_SMEM>>>(pxh, pxl, pWh + 2 * WSZ, pWl + 2 * WSZ,
                                           nullptr, pVth, pVtl, 1.0f);

    dim3 agrid(T_SEQ / 64, NHEADS);  // (64, 16)
    attn_mma<<<agrid, 128, ATTN_SMEM>>>(pQh, pQl, pKh, pKl, pVth, pVtl, paoh, paol);

    gemm_mma<0><<<ggrid, 256, GEMM_SMEM>>>(paoh, paol, pWh + 3 * WSZ, pWl + 3 * WSZ,
                                           out, nullptr, nullptr, 1.0f);
}

// round 5
// speedup vs baseline: 2.3347x; 1.0197x over previous
#include <cuda_runtime.h>
#include <cuda_bf16.h>
#include <cstdint>
#include <math.h>

#define T_SEQ 4096
#define DMODEL 1024
#define NHEADS 16
#define DH 64
#define WIN 256

// ---------------------------------------------------------------------------
// Scratch (__device__ globals; allocation-free rule)
// ---------------------------------------------------------------------------
__device__ __align__(16) __nv_bfloat16 g_xh[T_SEQ * DMODEL];
__device__ __align__(16) __nv_bfloat16 g_xl[T_SEQ * DMODEL];
__device__ __align__(16) __nv_bfloat16 g_Wh[4 * DMODEL * DMODEL];
__device__ __align__(16) __nv_bfloat16 g_Wl[4 * DMODEL * DMODEL];
__device__ __align__(16) __nv_bfloat16 g_aoh[T_SEQ * DMODEL];
__device__ __align__(16) __nv_bfloat16 g_aol[T_SEQ * DMODEL];
// Q/K head-major [h][t][d], V transposed [h][d][t]; all bf16 hi/lo
__device__ __align__(16) __nv_bfloat16 g_Qh[NHEADS * T_SEQ * DH];
__device__ __align__(16) __nv_bfloat16 g_Ql[NHEADS * T_SEQ * DH];
__device__ __align__(16) __nv_bfloat16 g_Kh[NHEADS * T_SEQ * DH];
__device__ __align__(16) __nv_bfloat16 g_Kl[NHEADS * T_SEQ * DH];
__device__ __align__(16) __nv_bfloat16 g_Vth[NHEADS * DH * T_SEQ];
__device__ __align__(16) __nv_bfloat16 g_Vtl[NHEADS * DH * T_SEQ];

// ---------------------------------------------------------------------------
// PTX helpers (generic PTX only — no tcgen05 on compute_103 virtual arch)
// ---------------------------------------------------------------------------
__device__ __forceinline__ uint32_t smem_u32(const void* p) {
    uint32_t a;
    asm("{ .reg .u64 t; cvta.to.shared.u64 t, %1; cvt.u32.u64 %0, t; }"
        : "=r"(a) : "l"(p));
    return a;
}

__device__ __forceinline__ void cp16(uint32_t dst, const void* src) {
    asm volatile("cp.async.cg.shared.global [%0], [%1], 16;" :: "r"(dst), "l"(src));
}
#define CP_COMMIT() asm volatile("cp.async.commit_group;" ::: "memory")
#define CP_WAIT(n)  asm volatile("cp.async.wait_group %0;" :: "n"(n) : "memory")

__device__ __forceinline__ void ldsm4(uint32_t (&r)[4], uint32_t addr) {
    asm volatile("ldmatrix.sync.aligned.m8n8.x4.shared.b16 {%0,%1,%2,%3}, [%4];"
                 : "=r"(r[0]), "=r"(r[1]), "=r"(r[2]), "=r"(r[3]) : "r"(addr));
}

__device__ __forceinline__ void mma16816(float (&d)[4], const uint32_t (&a)[4],
                                         uint32_t b0, uint32_t b1) {
    asm volatile(
        "mma.sync.aligned.m16n8k16.row.col.f32.bf16.bf16.f32 "
        "{%0,%1,%2,%3}, {%4,%5,%6,%7}, {%8,%9}, {%0,%1,%2,%3};"
        : "+f"(d[0]), "+f"(d[1]), "+f"(d[2]), "+f"(d[3])
        : "r"(a[0]), "r"(a[1]), "r"(a[2]), "r"(a[3]), "r"(b0), "r"(b1));
}

__device__ __forceinline__ uint32_t packbf(float x, float y) {
    unsigned short lx = __bfloat16_as_ushort(__float2bfloat16(x));
    unsigned short ly = __bfloat16_as_ushort(__float2bfloat16(y));
    return (uint32_t)lx | ((uint32_t)ly << 16);
}

// ---------------------------------------------------------------------------
// fp32 -> (hi, lo) bf16 splits
// ---------------------------------------------------------------------------
__device__ __forceinline__ void split4(const float* __restrict__ in,
                                       __nv_bfloat16* __restrict__ hi,
                                       __nv_bfloat16* __restrict__ lo, int i) {
    float4 v = ((const float4*)in)[i];
    float f[4] = {v.x, v.y, v.z, v.w};
    unsigned short h[4], l[4];
#pragma unroll
    for (int j = 0; j < 4; j++) {
        __nv_bfloat16 hb = __float2bfloat16(f[j]);
        __nv_bfloat16 lb = __float2bfloat16(f[j] - __bfloat162float(hb));
        h[j] = __bfloat16_as_ushort(hb);
        l[j] = __bfloat16_as_ushort(lb);
    }
    uint2 uh, ul;
    uh.x = (uint32_t)h[0] | ((uint32_t)h[1] << 16);
    uh.y = (uint32_t)h[2] | ((uint32_t)h[3] << 16);
    ul.x = (uint32_t)l[0] | ((uint32_t)l[1] << 16);
    ul.y = (uint32_t)l[2] | ((uint32_t)l[3] << 16);
    ((uint2*)hi)[i] = uh;
    ((uint2*)lo)[i] = ul;
}

__global__ void splitk(const float* __restrict__ in,
                       __nv_bfloat16* __restrict__ hi,
                       __nv_bfloat16* __restrict__ lo, int n4) {
    int i = blockIdx.x * 256 + threadIdx.x;
    if (i < n4) split4(in, hi, lo, i);
}

// all 4 weights in one launch (blockIdx.y selects the weight)
__global__ void splitW(const float* __restrict__ W0, const float* __restrict__ W1,
                       const float* __restrict__ W2, const float* __restrict__ W3,
                       __nv_bfloat16* __restrict__ hi, __nv_bfloat16* __restrict__ lo) {
    const int w = blockIdx.y;
    const float* src = (w == 0) ? W0 : (w == 1) ? W1 : (w == 2) ? W2 : W3;
    const int WSZ = DMODEL * DMODEL;
    int i = blockIdx.x * 256 + threadIdx.x;
    split4(src, hi + (size_t)w * WSZ, lo + (size_t)w * WSZ, i);
}

// ---------------------------------------------------------------------------
// Warp-mma split-bf16 GEMM: C[m,n] = sum_k A[m,k]*B[n,k]
// CTA 256x128, 8 warps (warp tile 64x64, 4m x 2n), KC=32, 3-stage cp.async.
// EPI 0: fp32 row-major.  EPI 1: bf16 hi/lo head-major [h][t][d] (*scale).
// EPI 2: bf16 hi/lo transposed [h][d][t] via smem staging.
// ---------------------------------------------------------------------------
#define KC 32
#define ROWB 80
#define A_ROWS 256
#define B_ROWS 128
#define A_TILE (A_ROWS * ROWB)                 // 20480
#define B_TILE (B_ROWS * ROWB)                 // 10240
#define STAGE_B (2 * A_TILE + 2 * B_TILE)      // 61440
#define NSTAGE 3
#define GEMM_SMEM (NSTAGE * STAGE_B)           // 184320
#define NCH (DMODEL / KC)                      // 32

__device__ __forceinline__ void gemm_issue(
    uint32_t sb, int stage, int chunk,
    const __nv_bfloat16* __restrict__ Ah, const __nv_bfloat16* __restrict__ Al,
    const __nv_bfloat16* __restrict__ Bh, const __nv_bfloat16* __restrict__ Bl,
    int bm, int bn, int tid) {
    const uint32_t st = sb + (uint32_t)stage * STAGE_B;
    const __nv_bfloat16* aArr[2] = {Ah + (size_t)bm * DMODEL, Al + (size_t)bm * DMODEL};
    const __nv_bfloat16* bArr[2] = {Bh + (size_t)bn * DMODEL, Bl + (size_t)bn * DMODEL};
#pragma unroll
    for (int t = 0; t < 2; t++) {
#pragma unroll
        for (int i = 0; i < 4; i++) {           // 256 rows * 4 segs / 256 thr
            int slot = tid + i * 256;
            int row = slot >> 2, seg = slot & 3;
            uint32_t dst = st + (uint32_t)t * A_TILE + row * ROWB + seg * 16;
            cp16(dst, aArr[t] + (size_t)row * DMODEL + chunk * KC + seg * 8);
        }
#pragma unroll
        for (int i = 0; i < 2; i++) {           // 128 rows * 4 segs / 256 thr
            int slot = tid + i * 256;
            int row = slot >> 2, seg = slot & 3;
            uint32_t dst = st + 2 * A_TILE + (uint32_t)t * B_TILE + row * ROWB + seg * 16;
            cp16(dst, bArr[t] + (size_t)row * DMODEL + chunk * KC + seg * 8);
        }
    }
    CP_COMMIT();
}

template <int EPI>
__global__ void __launch_bounds__(256)
gemm_mma(const __nv_bfloat16* __restrict__ Ah, const __nv_bfloat16* __restrict__ Al,
         const __nv_bfloat16* __restrict__ Bh, const __nv_bfloat16* __restrict__ Bl,
         float* __restrict__ Cf, __nv_bfloat16* __restrict__ Ch,
         __nv_bfloat16* __restrict__ Cl, float scale) {
    extern __shared__ char smraw[];
    const uint32_t sb = smem_u32(smraw);

    const int tid = threadIdx.x;
    const int warp = tid >> 5;
    const int lane = tid & 31;
    const int bm = blockIdx.y * 256;
    const int bn = blockIdx.x * 128;
    const int wm = (warp >> 1) * 64;   // 0,64,128,192
    const int wn = (warp & 1) * 64;    // 0,64

    float acc[4][8][4];
#pragma unroll
    for (int i = 0; i < 4; i++)
#pragma unroll
        for (int j = 0; j < 8; j++)
#pragma unroll
            for (int e = 0; e < 4; e++) acc[i][j][e] = 0.0f;

    const int lrow = lane & 15;
    const int lseg = lane >> 4;

    gemm_issue(sb, 0, 0, Ah, Al, Bh, Bl, bm, bn, tid);
    gemm_issue(sb, 1, 1, Ah, Al, Bh, Bl, bm, bn, tid);
    gemm_issue(sb, 2, 2, Ah, Al, Bh, Bl, bm, bn, tid);

    int stage = 0;
    for (int c = 0; c < NCH; c++) {
        if (c <= NCH - 3) { CP_WAIT(2); }
        else if (c == NCH - 2) { CP_WAIT(1); }
        else { CP_WAIT(0); }
        __syncthreads();

        const uint32_t st = sb + (uint32_t)stage * STAGE_B;
#pragma unroll
        for (int kk = 0; kk < 2; kk++) {
            uint32_t ah[4][4], al[4][4];
            uint32_t bh[4][4], bl[4][4];
#pragma unroll
            for (int mi = 0; mi < 4; mi++) {
                uint32_t ad = st + (wm + mi * 16 + lrow) * ROWB + kk * 32 + lseg * 16;
                ldsm4(ah[mi], ad);
                ldsm4(al[mi], ad + A_TILE);
            }
#pragma unroll
            for (int n16 = 0; n16 < 4; n16++) {
                uint32_t ad = st + 2 * A_TILE + (wn + n16 * 16 + lrow) * ROWB +
                              kk * 32 + lseg * 16;
                ldsm4(bh[n16], ad);
                ldsm4(bl[n16], ad + B_TILE);
            }
#pragma unroll
            for (int mi = 0; mi < 4; mi++)
#pragma unroll
                for (int nj = 0; nj < 8; nj++) {
                    const int nh = nj >> 1, sub = nj & 1;
                    mma16816(acc[mi][nj], ah[mi], bh[nh][sub], bh[nh][sub + 2]);
                    mma16816(acc[mi][nj], ah[mi], bl[nh][sub], bl[nh][sub + 2]);
                    mma16816(acc[mi][nj], al[mi], bh[nh][sub], bh[nh][sub + 2]);
                }
        }
        __syncthreads();
        if (c + 3 < NCH)
            gemm_issue(sb, stage, c + 3, Ah, Al, Bh, Bl, bm, bn, tid);
        stage = (stage == 2) ? 0 : stage + 1;
    }

    if (EPI == 0) {
        const int r0 = bm + wm + (lane >> 2);
        const int c0 = bn + wn + (lane & 3) * 2;
#pragma unroll
        for (int mi = 0; mi < 4; mi++)
#pragma unroll
            for (int nj = 0; nj < 8; nj++) {
                const int r = r0 + mi * 16;
                const int cc = c0 + nj * 8;
                float* d0 = Cf + (size_t)r * DMODEL + cc;
                float* d1 = Cf + (size_t)(r + 8) * DMODEL + cc;
                *(float2*)d0 = make_float2(acc[mi][nj][0], acc[mi][nj][1]);
                *(float2*)d1 = make_float2(acc[mi][nj][2], acc[mi][nj][3]);
            }
    } else if (EPI == 1) {
        const int r0 = bm + wm + (lane >> 2);
        const int c0 = bn + wn + (lane & 3) * 2;
#pragma unroll
        for (int mi = 0; mi < 4; mi++)
#pragma unroll
            for (int nj = 0; nj < 8; nj++) {
                const int r = r0 + mi * 16;
                const int cc = c0 + nj * 8;
                const int h = cc >> 6;
                const int cl = cc & 63;
#pragma unroll
                for (int half = 0; half < 2; half++) {
                    float v0 = acc[mi][nj][half * 2 + 0] * scale;
                    float v1 = acc[mi][nj][half * 2 + 1] * scale;
                    __nv_bfloat16 h0 = __float2bfloat16(v0);
                    __nv_bfloat16 h1 = __float2bfloat16(v1);
                    size_t base = ((size_t)(h * T_SEQ + r + half * 8) << 6) + cl;
                    *(uint32_t*)(Ch + base) =
                        (uint32_t)__bfloat16_as_ushort(h0) |
                        ((uint32_t)__bfloat16_as_ushort(h1) << 16);
                    *(uint32_t*)(Cl + base) =
                        packbf(v0 - __bfloat162float(h0), v1 - __bfloat162float(h1));
                }
            }
    } else {
        // EPI 2: transpose to [h][d][t] via smem staging (reuse pipeline smem)
        __syncthreads();
        __nv_bfloat16* sVh = (__nv_bfloat16*)smraw;        // [128 cols][264]
        __nv_bfloat16* sVl = sVh + 128 * 264;
        const int lr0 = wm + (lane >> 2);
        const int lc0 = wn + (lane & 3) * 2;
#pragma unroll
        for (int mi = 0; mi < 4; mi++)
#pragma unroll
            for (int nj = 0; nj < 8; nj++) {
                const int lc = lc0 + nj * 8;
#pragma unroll
                for (int half = 0; half < 2; half++) {
                    float v0 = acc[mi][nj][half * 2 + 0];
                    float v1 = acc[mi][nj][half * 2 + 1];
                    __nv_bfloat16 h0 = __float2bfloat16(v0);
                    __nv_bfloat16 h1 = __float2bfloat16(v1);
                    int rr = lr0 + mi * 16 + half * 8;
                    sVh[lc * 264 + rr] = h0;
                    sVh[(lc + 1) * 264 + rr] = h1;
                    sVl[lc * 264 + rr] = __float2bfloat16(v0 - __bfloat162float(h0));
                    sVl[(lc + 1) * 264 + rr] = __float2bfloat16(v1 - __bfloat162float(h1));
                }
            }
        __syncthreads();
        for (int i = tid; i < 128 * 32; i += 256) {
            int row = i >> 5, seg = i & 31;      // row: local n (0..127), seg: 8-elt chunk
            int gn = bn + row;
            int hh = gn >> 6, dd = gn & 63;
            size_t dst = (size_t)(hh * DH + dd) * T_SEQ + bm + seg * 8;
            *(uint4*)(Ch + dst) = *(uint4*)(sVh + row * 264 + seg * 8);
            *(uint4*)(Cl + dst) = *(uint4*)(sVl + row * 264 + seg * 8);
        }
    }
}

// ---------------------------------------------------------------------------
// HMMA sliding-window attention (unchanged from R4 — proven @ ~85us)
// ---------------------------------------------------------------------------
#define AROWB 176
#define ATILE (64 * AROWB)
#define ASTAGE (4 * ATILE)
#define ATTN_SMEM (2 * ASTAGE)
#define OFF_KH 0
#define OFF_KL ATILE
#define OFF_VH (2 * ATILE)
#define OFF_VL (3 * ATILE)

__device__ __forceinline__ void attn_load_tile(
    uint32_t base, const __nv_bfloat16* __restrict__ Kh,
    const __nv_bfloat16* __restrict__ Kl,
    const __nv_bfloat16* __restrict__ Vth,
    const __nv_bfloat16* __restrict__ Vtl,
    int h, int kt, int tid) {
#pragma unroll
    for (int i = 0; i < 4; i++) {
        int idx = tid + i * 128;
        int row = idx >> 3, seg = idx & 7;
        uint32_t dk = base + OFF_KH + row * AROWB + seg * 16;
        size_t ks = ((size_t)(h * T_SEQ + kt + row) << 6) + seg * 8;
        cp16(dk, Kh + ks);
        cp16(dk + ATILE, Kl + ks);
        uint32_t dv = base + OFF_VH + row * AROWB + seg * 16;
        size_t vs = (size_t)(h * DH + row) * T_SEQ + kt + seg * 8;
        cp16(dv, Vth + vs);
        cp16(dv + ATILE, Vtl + vs);
    }
    CP_COMMIT();
}

__global__ void __launch_bounds__(128)
attn_mma(const __nv_bfloat16* __restrict__ Qh, const __nv_bfloat16* __restrict__ Ql,
         const __nv_bfloat16* __restrict__ Kh, const __nv_bfloat16* __restrict__ Kl,
         const __nv_bfloat16* __restrict__ Vth, const __nv_bfloat16* __restrict__ Vtl,
         __nv_bfloat16* __restrict__ AOh, __nv_bfloat16* __restrict__ AOl) {
    extern __shared__ char smraw[];
    const uint32_t sb = smem_u32(smraw);
    const int tid = threadIdx.x;
    const int warp = tid >> 5;
    const int lane = tid & 31;
    const int h = blockIdx.y;
    const int q0 = blockIdx.x * 64;
    const int lrow = lane & 15;
    const int lseg = lane >> 4;

#pragma unroll
    for (int i = 0; i < 4; i++) {
        int idx = tid + i * 128;
        int row = idx >> 3, seg = idx & 7;
        uint32_t dst = sb + OFF_KH + row * AROWB + seg * 16;
        size_t qs = ((size_t)(h * T_SEQ + q0 + row) << 6) + seg * 8;
        cp16(dst, Qh + qs);
        cp16(dst + ATILE, Ql + qs);
    }
    CP_COMMIT();
    CP_WAIT(0);
    __syncthreads();

    uint32_t qfh[4][4], qfl[4][4];
#pragma unroll
    for (int k = 0; k < 4; k++) {
        uint32_t ad = sb + (warp * 16 + lrow) * AROWB + k * 32 + lseg * 16;
        ldsm4(qfh[k], ad);
        ldsm4(qfl[k], ad + ATILE);
    }
    __syncthreads();

    float o[8][4];
#pragma unroll
    for (int j = 0; j < 8; j++)
#pragma unroll
        for (int e = 0; e < 4; e++) o[j][e] = 0.0f;
    float m0 = -1e30f, m1 = -1e30f, l0 = 0.0f, l1 = 0.0f;

    const int kt_lo = (q0 >= WIN) ? (q0 - WIN) : 0;
    const int ntiles = (q0 - kt_lo) / 64 + 1;

    attn_load_tile(sb, Kh, Kl, Vth, Vtl, h, kt_lo, tid);
    if (ntiles > 1) attn_load_tile(sb + ASTAGE, Kh, Kl, Vth, Vtl, h, kt_lo + 64, tid);

    for (int ti = 0; ti < ntiles; ti++) {
        const int kt = kt_lo + ti * 64;
        const uint32_t base = sb + (uint32_t)(ti & 1) * ASTAGE;
        if (ti + 1 < ntiles) { CP_WAIT(1); } else { CP_WAIT(0); }
        __syncthreads();

        float sf[8][4];
#pragma unroll
        for (int j = 0; j < 8; j++)
#pragma unroll
            for (int e = 0; e < 4; e++) sf[j][e] = 0.0f;
#pragma unroll
        for (int kk = 0; kk < 4; kk++) {
            uint32_t bh[4][4], bl[4][4];
#pragma unroll
            for (int n16 = 0; n16 < 4; n16++) {
                uint32_t ad = base + OFF_KH + (n16 * 16 + lrow) * AROWB + kk * 32 + lseg * 16;
                ldsm4(bh[n16], ad);
                ldsm4(bl[n16], ad + ATILE);
            }
#pragma unroll
            for (int j = 0; j < 8; j++) {
                const int nh = j >> 1, sub = j & 1;
                mma16816(sf[j], qfh[kk], bh[nh][sub], bh[nh][sub + 2]);
                mma16816(sf[j], qfh[kk], bl[nh][sub], bl[nh][sub + 2]);
                mma16816(sf[j], qfl[kk], bh[nh][sub], bh[nh][sub + 2]);
            }
        }

        const int r0 = q0 + warp * 16 + (lane >> 2);
        const int r1 = r0 + 8;
#pragma unroll
        for (int j = 0; j < 8; j++) {
            const int c0 = kt + 8 * j + (lane & 3) * 2;
            const int c1 = c0 + 1;
            if (c0 > r0 || c0 < r0 - WIN) sf[j][0] = -1e30f;
            if (c1 > r0 || c1 < r0 - WIN) sf[j][1] = -1e30f;
            if (c0 > r1 || c0 < r1 - WIN) sf[j][2] = -1e30f;
            if (c1 > r1 || c1 < r1 - WIN) sf[j][3] = -1e30f;
        }

        float t0 = -1e30f, t1 = -1e30f;
#pragma unroll
        for (int j = 0; j < 8; j++) {
            t0 = fmaxf(t0, fmaxf(sf[j][0], sf[j][1]));
            t1 = fmaxf(t1, fmaxf(sf[j][2], sf[j][3]));
        }
        t0 = fmaxf(t0, __shfl_xor_sync(0xffffffffu, t0, 1));
        t0 = fmaxf(t0, __shfl_xor_sync(0xffffffffu, t0, 2));
        t1 = fmaxf(t1, __shfl_xor_sync(0xffffffffu, t1, 1));
        t1 = fmaxf(t1, __shfl_xor_sync(0xffffffffu, t1, 2));
        const float mn0 = fmaxf(m0, t0), mn1 = fmaxf(m1, t1);
        const float corr0 = __expf(m0 - mn0), corr1 = __expf(m1 - mn1);
        m0 = mn0;
        m1 = mn1;

        uint32_t ph[4][4], pl[4][4];
        float s0 = 0.0f, s1 = 0.0f;
#pragma unroll
        for (int j = 0; j < 8; j++) {
            float p0 = __expf(sf[j][0] - m0);
            float p1 = __expf(sf[j][1] - m0);
            float p2 = __expf(sf[j][2] - m1);
            float p3 = __expf(sf[j][3] - m1);
            s0 += p0 + p1;
            s1 += p2 + p3;
            __nv_bfloat16 b0 = __float2bfloat16(p0), b1 = __float2bfloat16(p1);
            __nv_bfloat16 b2 = __float2bfloat16(p2), b3 = __float2bfloat16(p3);
            const int kk = j >> 1, pos = (j & 1) * 2;
            ph[kk][pos + 0] = (uint32_t)__bfloat16_as_ushort(b0) |
                              ((uint32_t)__bfloat16_as_ushort(b1) << 16);
            ph[kk][pos + 1] = (uint32_t)__bfloat16_as_ushort(b2) |
                              ((uint32_t)__bfloat16_as_ushort(b3) << 16);
            pl[kk][pos + 0] = packbf(p0 - __bfloat162float(b0), p1 - __bfloat162float(b1));
            pl[kk][pos + 1] = packbf(p2 - __bfloat162float(b2), p3 - __bfloat162float(b3));
        }
        s0 += __shfl_xor_sync(0xffffffffu, s0, 1);
        s0 += __shfl_xor_sync(0xffffffffu, s0, 2);
        s1 += __shfl_xor_sync(0xffffffffu, s1, 1);
        s1 += __shfl_xor_sync(0xffffffffu, s1, 2);
        l0 = l0 * corr0 + s0;
        l1 = l1 * corr1 + s1;
#pragma unroll
        for (int j = 0; j < 8; j++) {
            o[j][0] *= corr0;
            o[j][1] *= corr0;
            o[j][2] *= corr1;
            o[j][3] *= corr1;
        }

#pragma unroll
        for (int kk = 0; kk < 4; kk++) {
            uint32_t vh[4][4], vl[4][4];
#pragma unroll
            for (int n16 = 0; n16 < 4; n16++) {
                uint32_t ad = base + OFF_VH + (n16 * 16 + lrow) * AROWB + kk * 32 + lseg * 16;
                ldsm4(vh[n16], ad);
                ldsm4(vl[n16], ad + ATILE);
            }
#pragma unroll
            for (int j = 0; j < 8; j++) {
                const int nh = j >> 1, sub = j & 1;
                mma16816(o[j], ph[kk], vh[nh][sub], vh[nh][sub + 2]);
                mma16816(o[j], ph[kk], vl[nh][sub], vl[nh][sub + 2]);
                mma16816(o[j], pl[kk], vh[nh][sub], vh[nh][sub + 2]);
            }
        }
        __syncthreads();
        if (ti + 2 < ntiles)
            attn_load_tile(sb + (uint32_t)(ti & 1) * ASTAGE, Kh, Kl, Vth, Vtl, h,
                           kt + 128, tid);
    }

    const float i0 = 1.0f / l0;
    const float i1 = 1.0f / l1;
    const int tr = q0 + warp * 16 + (lane >> 2);
#pragma unroll
    for (int j = 0; j < 8; j++) {
        const int d = 8 * j + (lane & 3) * 2;
        float v0 = o[j][0] * i0, v1 = o[j][1] * i0;
        float v2 = o[j][2] * i1, v3 = o[j][3] * i1;
        __nv_bfloat16 h0 = __float2bfloat16(v0), h1 = __float2bfloat16(v1);
        __nv_bfloat16 h2 = __float2bfloat16(v2), h3 = __float2bfloat16(v3);
        size_t a0 = (size_t)tr * DMODEL + h * DH + d;
        size_t a1 = (size_t)(tr + 8) * DMODEL + h * DH + d;
        *(uint32_t*)(AOh + a0) = (uint32_t)__bfloat16_as_ushort(h0) |
                                 ((uint32_t)__bfloat16_as_ushort(h1) << 16);
        *(uint32_t*)(AOh + a1) = (uint32_t)__bfloat16_as_ushort(h2) |
                                 ((uint32_t)__bfloat16_as_ushort(h3) << 16);
        *(uint32_t*)(AOl + a0) = packbf(v0 - __bfloat162float(h0), v1 - __bfloat162float(h1));
        *(uint32_t*)(AOl + a1) = packbf(v2 - __bfloat162float(h2), v3 - __bfloat162float(h3));
    }
}

// ---------------------------------------------------------------------------
extern "C" void kernel_launch(void* const* d_in, const int* in_sizes, int n_in,
                              void* d_out, int out_size) {
    const float* x  = (const float*)d_in[0];
    const float* Wq = (const float*)d_in[1];
    const float* Wk = (const float*)d_in[2];
    const float* Wv = (const float*)d_in[3];
    const float* Wo = (const float*)d_in[4];
    float* out = (float*)d_out;

    __nv_bfloat16 *pxh, *pxl, *pWh, *pWl, *paoh, *paol;
    __nv_bfloat16 *pQh, *pQl, *pKh, *pKl, *pVth, *pVtl;
    cudaGetSymbolAddress((void**)&pxh, g_xh);
    cudaGetSymbolAddress((void**)&pxl, g_xl);
    cudaGetSymbolAddress((void**)&pWh, g_Wh);
    cudaGetSymbolAddress((void**)&pWl, g_Wl);
    cudaGetSymbolAddress((void**)&paoh, g_aoh);
    cudaGetSymbolAddress((void**)&paol, g_aol);
    cudaGetSymbolAddress((void**)&pQh, g_Qh);
    cudaGetSymbolAddress((void**)&pQl, g_Ql);
    cudaGetSymbolAddress((void**)&pKh, g_Kh);
    cudaGetSymbolAddress((void**)&pKl, g_Kl);
    cudaGetSymbolAddress((void**)&pVth, g_Vth);
    cudaGetSymbolAddress((void**)&pVtl, g_Vtl);

    cudaFuncSetAttribute(gemm_mma<0>, cudaFuncAttributeMaxDynamicSharedMemorySize, GEMM_SMEM);
    cudaFuncSetAttribute(gemm_mma<1>, cudaFuncAttributeMaxDynamicSharedMemorySize, GEMM_SMEM);
    cudaFuncSetAttribute(gemm_mma<2>, cudaFuncAttributeMaxDynamicSharedMemorySize, GEMM_SMEM);
    cudaFuncSetAttribute(attn_mma, cudaFuncAttributeMaxDynamicSharedMemorySize, ATTN_SMEM);

    const int n4x = T_SEQ * DMODEL / 4;
    const int n4w = DMODEL * DMODEL / 4;
    const int WSZ = DMODEL * DMODEL;

    splitk<<<n4x / 256, 256>>>(x, pxh, pxl, n4x);
    dim3 wgrid(n4w / 256, 4);
    splitW<<<wgrid, 256>>>(Wq, Wk, Wv, Wo, pWh, pWl);

    dim3 ggrid(DMODEL / 128, T_SEQ / 256);  // (8, 16) = 128 CTAs, one wave
    gemm_mma<1><<<ggrid, 256, GEMM_SMEM>>>(pxh, pxl, pWh + 0 * WSZ, pWl + 0 * WSZ,
                                           nullptr, pQh, pQl, 0.125f);
    gemm_mma<1><<<ggrid, 256, GEMM_SMEM>>>(pxh, pxl, pWh + 1 * WSZ, pWl + 1 * WSZ,
                                           nullptr, pKh, pKl, 1.0f);
    gemm_mma<2><<<ggrid, 256, GEMM_SMEM>>>(pxh, pxl, pWh + 2 * WSZ, pWl + 2 * WSZ,
                                           nullptr, pVth, pVtl, 1.0f);

    dim3 agrid(T_SEQ / 64, NHEADS);  // (64, 16)
    attn_mma<<<agrid, 128, ATTN_SMEM>>>(pQh, pQl, pKh, pKl, pVth, pVtl, paoh, paol);

    gemm_mma<0><<<ggrid, 256, GEMM_SMEM>>>(paoh, paol, pWh + 3 * WSZ, pWl + 3 * WSZ,
                                           out, nullptr, nullptr, 1.0f);
}

// round 6
// speedup vs baseline: 2.3832x; 1.0208x over previous
#include <cuda_runtime.h>
#include <cuda_bf16.h>
#include <cstdint>
#include <math.h>

#define T_SEQ 4096
#define DMODEL 1024
#define NHEADS 16
#define DH 64
#define WIN 256

// ---------------------------------------------------------------------------
// Scratch (__device__ globals; allocation-free rule)
// ---------------------------------------------------------------------------
__device__ __align__(16) __nv_bfloat16 g_xh[T_SEQ * DMODEL];
__device__ __align__(16) __nv_bfloat16 g_xl[T_SEQ * DMODEL];
__device__ __align__(16) __nv_bfloat16 g_Wh[4 * DMODEL * DMODEL];
__device__ __align__(16) __nv_bfloat16 g_Wl[4 * DMODEL * DMODEL];
__device__ __align__(16) __nv_bfloat16 g_aoh[T_SEQ * DMODEL];
__device__ __align__(16) __nv_bfloat16 g_aol[T_SEQ * DMODEL];
__device__ __align__(16) __nv_bfloat16 g_Qh[NHEADS * T_SEQ * DH];
__device__ __align__(16) __nv_bfloat16 g_Ql[NHEADS * T_SEQ * DH];
__device__ __align__(16) __nv_bfloat16 g_Kh[NHEADS * T_SEQ * DH];
__device__ __align__(16) __nv_bfloat16 g_Kl[NHEADS * T_SEQ * DH];
__device__ __align__(16) __nv_bfloat16 g_Vth[NHEADS * DH * T_SEQ];
__device__ __align__(16) __nv_bfloat16 g_Vtl[NHEADS * DH * T_SEQ];

// ---------------------------------------------------------------------------
// PTX helpers (generic PTX only — no tcgen05 on compute_103 virtual arch)
// ---------------------------------------------------------------------------
__device__ __forceinline__ uint32_t smem_u32(const void* p) {
    uint32_t a;
    asm("{ .reg .u64 t; cvta.to.shared.u64 t, %1; cvt.u32.u64 %0, t; }"
        : "=r"(a) : "l"(p));
    return a;
}

__device__ __forceinline__ void cp16(uint32_t dst, const void* src) {
    asm volatile("cp.async.cg.shared.global [%0], [%1], 16;" :: "r"(dst), "l"(src));
}
#define CP_COMMIT() asm volatile("cp.async.commit_group;" ::: "memory")
#define CP_WAIT(n)  asm volatile("cp.async.wait_group %0;" :: "n"(n) : "memory")

__device__ __forceinline__ void ldsm4(uint32_t (&r)[4], uint32_t addr) {
    asm volatile("ldmatrix.sync.aligned.m8n8.x4.shared.b16 {%0,%1,%2,%3}, [%4];"
                 : "=r"(r[0]), "=r"(r[1]), "=r"(r[2]), "=r"(r[3]) : "r"(addr));
}

__device__ __forceinline__ void mma16816(float (&d)[4], const uint32_t (&a)[4],
                                         uint32_t b0, uint32_t b1) {
    asm volatile(
        "mma.sync.aligned.m16n8k16.row.col.f32.bf16.bf16.f32 "
        "{%0,%1,%2,%3}, {%4,%5,%6,%7}, {%8,%9}, {%0,%1,%2,%3};"
        : "+f"(d[0]), "+f"(d[1]), "+f"(d[2]), "+f"(d[3])
        : "r"(a[0]), "r"(a[1]), "r"(a[2]), "r"(a[3]), "r"(b0), "r"(b1));
}

__device__ __forceinline__ uint32_t packbf(float x, float y) {
    unsigned short lx = __bfloat16_as_ushort(__float2bfloat16(x));
    unsigned short ly = __bfloat16_as_ushort(__float2bfloat16(y));
    return (uint32_t)lx | ((uint32_t)ly << 16);
}

// ---------------------------------------------------------------------------
// fp32 -> (hi, lo) bf16 splits
// ---------------------------------------------------------------------------
__device__ __forceinline__ void split4(const float* __restrict__ in,
                                       __nv_bfloat16* __restrict__ hi,
                                       __nv_bfloat16* __restrict__ lo, int i) {
    float4 v = ((const float4*)in)[i];
    float f[4] = {v.x, v.y, v.z, v.w};
    unsigned short h[4], l[4];
#pragma unroll
    for (int j = 0; j < 4; j++) {
        __nv_bfloat16 hb = __float2bfloat16(f[j]);
        __nv_bfloat16 lb = __float2bfloat16(f[j] - __bfloat162float(hb));
        h[j] = __bfloat16_as_ushort(hb);
        l[j] = __bfloat16_as_ushort(lb);
    }
    uint2 uh, ul;
    uh.x = (uint32_t)h[0] | ((uint32_t)h[1] << 16);
    uh.y = (uint32_t)h[2] | ((uint32_t)h[3] << 16);
    ul.x = (uint32_t)l[0] | ((uint32_t)l[1] << 16);
    ul.y = (uint32_t)l[2] | ((uint32_t)l[3] << 16);
    ((uint2*)hi)[i] = uh;
    ((uint2*)lo)[i] = ul;
}

__global__ void splitk(const float* __restrict__ in,
                       __nv_bfloat16* __restrict__ hi,
                       __nv_bfloat16* __restrict__ lo, int n4) {
    int i = blockIdx.x * 256 + threadIdx.x;
    if (i < n4) split4(in, hi, lo, i);
}

__global__ void splitW(const float* __restrict__ W0, const float* __restrict__ W1,
                       const float* __restrict__ W2, const float* __restrict__ W3,
                       __nv_bfloat16* __restrict__ hi, __nv_bfloat16* __restrict__ lo) {
    const int w = blockIdx.y;
    const float* src = (w == 0) ? W0 : (w == 1) ? W1 : (w == 2) ? W2 : W3;
    const int WSZ = DMODEL * DMODEL;
    int i = blockIdx.x * 256 + threadIdx.x;
    split4(src, hi + (size_t)w * WSZ, lo + (size_t)w * WSZ, i);
}

// ---------------------------------------------------------------------------
// Warp-mma split-bf16 GEMM: C[m,n] = sum_k A[m,k]*B[n,k]
// CTA 256x128, 512 threads / 16 warps (4m x 4n), warp tile 64x32, KC=32,
// 3-stage cp.async pipeline. Term-reordered MMAs (RAW distance 16).
// EPI 0: fp32 row-major.  EPI 1: bf16 hi/lo head-major [h][t][d] (*scale).
// EPI 2: bf16 hi/lo transposed [h][d][t] via smem staging.
// ---------------------------------------------------------------------------
#define KC 32
#define ROWB 80
#define A_ROWS 256
#define B_ROWS 128
#define A_TILE (A_ROWS * ROWB)                 // 20480
#define B_TILE (B_ROWS * ROWB)                 // 10240
#define STAGE_B (2 * A_TILE + 2 * B_TILE)      // 61440
#define NSTAGE 3
#define GEMM_SMEM (NSTAGE * STAGE_B)           // 184320
#define NCH (DMODEL / KC)                      // 32
#define GTHREADS 512

__device__ __forceinline__ void gemm_issue(
    uint32_t sb, int stage, int chunk,
    const __nv_bfloat16* __restrict__ Ah, const __nv_bfloat16* __restrict__ Al,
    const __nv_bfloat16* __restrict__ Bh, const __nv_bfloat16* __restrict__ Bl,
    int bm, int bn, int tid) {
    const uint32_t st = sb + (uint32_t)stage * STAGE_B;
    const __nv_bfloat16* aArr[2] = {Ah + (size_t)bm * DMODEL, Al + (size_t)bm * DMODEL};
    const __nv_bfloat16* bArr[2] = {Bh + (size_t)bn * DMODEL, Bl + (size_t)bn * DMODEL};
#pragma unroll
    for (int t = 0; t < 2; t++) {
#pragma unroll
        for (int i = 0; i < 2; i++) {           // A: 256 rows * 4 segs / 512 thr
            int slot = tid + i * GTHREADS;
            int row = slot >> 2, seg = slot & 3;
            uint32_t dst = st + (uint32_t)t * A_TILE + row * ROWB + seg * 16;
            cp16(dst, aArr[t] + (size_t)row * DMODEL + chunk * KC + seg * 8);
        }
        {                                        // B: 128 rows * 4 segs / 512 thr
            int row = tid >> 2, seg = tid & 3;
            uint32_t dst = st + 2 * A_TILE + (uint32_t)t * B_TILE + row * ROWB + seg * 16;
            cp16(dst, bArr[t] + (size_t)row * DMODEL + chunk * KC + seg * 8);
        }
    }
    CP_COMMIT();
}

template <int EPI>
__global__ void __launch_bounds__(GTHREADS, 1)
gemm_mma(const __nv_bfloat16* __restrict__ Ah, const __nv_bfloat16* __restrict__ Al,
         const __nv_bfloat16* __restrict__ Bh, const __nv_bfloat16* __restrict__ Bl,
         float* __restrict__ Cf, __nv_bfloat16* __restrict__ Ch,
         __nv_bfloat16* __restrict__ Cl, float scale) {
    extern __shared__ char smraw[];
    const uint32_t sb = smem_u32(smraw);

    const int tid = threadIdx.x;
    const int warp = tid >> 5;
    const int lane = tid & 31;
    const int bm = blockIdx.y * 256;
    const int bn = blockIdx.x * 128;
    const int wm = (warp >> 2) * 64;   // 0,64,128,192
    const int wn = (warp & 3) * 32;    // 0,32,64,96

    float acc[4][4][4];
#pragma unroll
    for (int i = 0; i < 4; i++)
#pragma unroll
        for (int j = 0; j < 4; j++)
#pragma unroll
            for (int e = 0; e < 4; e++) acc[i][j][e] = 0.0f;

    const int lrow = lane & 15;
    const int lseg = lane >> 4;

    gemm_issue(sb, 0, 0, Ah, Al, Bh, Bl, bm, bn, tid);
    gemm_issue(sb, 1, 1, Ah, Al, Bh, Bl, bm, bn, tid);
    gemm_issue(sb, 2, 2, Ah, Al, Bh, Bl, bm, bn, tid);

    int stage = 0;
    for (int c = 0; c < NCH; c++) {
        if (c <= NCH - 3) { CP_WAIT(2); }
        else if (c == NCH - 2) { CP_WAIT(1); }
        else { CP_WAIT(0); }
        __syncthreads();

        const uint32_t st = sb + (uint32_t)stage * STAGE_B;
#pragma unroll
        for (int kk = 0; kk < 2; kk++) {
            uint32_t ah[4][4], al[4][4];
            uint32_t bh[2][4], bl[2][4];
#pragma unroll
            for (int mi = 0; mi < 4; mi++) {
                uint32_t ad = st + (wm + mi * 16 + lrow) * ROWB + kk * 32 + lseg * 16;
                ldsm4(ah[mi], ad);
                ldsm4(al[mi], ad + A_TILE);
            }
#pragma unroll
            for (int n16 = 0; n16 < 2; n16++) {
                uint32_t ad = st + 2 * A_TILE + (wn + n16 * 16 + lrow) * ROWB +
                              kk * 32 + lseg * 16;
                ldsm4(bh[n16], ad);
                ldsm4(bl[n16], ad + B_TILE);
            }
            // term-reordered: same-acc MMAs are 16 apart
#pragma unroll
            for (int mi = 0; mi < 4; mi++)
#pragma unroll
                for (int nj = 0; nj < 4; nj++) {
                    const int nh = nj >> 1, sub = nj & 1;
                    mma16816(acc[mi][nj], ah[mi], bh[nh][sub], bh[nh][sub + 2]);
                }
#pragma unroll
            for (int mi = 0; mi < 4; mi++)
#pragma unroll
                for (int nj = 0; nj < 4; nj++) {
                    const int nh = nj >> 1, sub = nj & 1;
                    mma16816(acc[mi][nj], ah[mi], bl[nh][sub], bl[nh][sub + 2]);
                }
#pragma unroll
            for (int mi = 0; mi < 4; mi++)
#pragma unroll
                for (int nj = 0; nj < 4; nj++) {
                    const int nh = nj >> 1, sub = nj & 1;
                    mma16816(acc[mi][nj], al[mi], bh[nh][sub], bh[nh][sub + 2]);
                }
        }
        __syncthreads();
        if (c + 3 < NCH)
            gemm_issue(sb, stage, c + 3, Ah, Al, Bh, Bl, bm, bn, tid);
        stage = (stage == 2) ? 0 : stage + 1;
    }

    if (EPI == 0) {
        const int r0 = bm + wm + (lane >> 2);
        const int c0 = bn + wn + (lane & 3) * 2;
#pragma unroll
        for (int mi = 0; mi < 4; mi++)
#pragma unroll
            for (int nj = 0; nj < 4; nj++) {
                const int r = r0 + mi * 16;
                const int cc = c0 + nj * 8;
                float* d0 = Cf + (size_t)r * DMODEL + cc;
                float* d1 = Cf + (size_t)(r + 8) * DMODEL + cc;
                *(float2*)d0 = make_float2(acc[mi][nj][0], acc[mi][nj][1]);
                *(float2*)d1 = make_float2(acc[mi][nj][2], acc[mi][nj][3]);
            }
    } else if (EPI == 1) {
        const int r0 = bm + wm + (lane >> 2);
        const int c0 = bn + wn + (lane & 3) * 2;
#pragma unroll
        for (int mi = 0; mi < 4; mi++)
#pragma unroll
            for (int nj = 0; nj < 4; nj++) {
                const int r = r0 + mi * 16;
                const int cc = c0 + nj * 8;
                const int h = cc >> 6;
                const int cl = cc & 63;
#pragma unroll
                for (int half = 0; half < 2; half++) {
                    float v0 = acc[mi][nj][half * 2 + 0] * scale;
                    float v1 = acc[mi][nj][half * 2 + 1] * scale;
                    __nv_bfloat16 h0 = __float2bfloat16(v0);
                    __nv_bfloat16 h1 = __float2bfloat16(v1);
                    size_t base = ((size_t)(h * T_SEQ + r + half * 8) << 6) + cl;
                    *(uint32_t*)(Ch + base) =
                        (uint32_t)__bfloat16_as_ushort(h0) |
                        ((uint32_t)__bfloat16_as_ushort(h1) << 16);
                    *(uint32_t*)(Cl + base) =
                        packbf(v0 - __bfloat162float(h0), v1 - __bfloat162float(h1));
                }
            }
    } else {
        // EPI 2: transpose to [h][d][t] via smem staging (reuse pipeline smem)
        __syncthreads();
        __nv_bfloat16* sVh = (__nv_bfloat16*)smraw;        // [128 n][264 m-pad]
        __nv_bfloat16* sVl = sVh + 128 * 264;
        const int lr0 = wm + (lane >> 2);
        const int lc0 = wn + (lane & 3) * 2;
#pragma unroll
        for (int mi = 0; mi < 4; mi++)
#pragma unroll
            for (int nj = 0; nj < 4; nj++) {
                const int lc = lc0 + nj * 8;
#pragma unroll
                for (int half = 0; half < 2; half++) {
                    float v0 = acc[mi][nj][half * 2 + 0];
                    float v1 = acc[mi][nj][half * 2 + 1];
                    __nv_bfloat16 h0 = __float2bfloat16(v0);
                    __nv_bfloat16 h1 = __float2bfloat16(v1);
                    int rr = lr0 + mi * 16 + half * 8;
                    sVh[lc * 264 + rr] = h0;
                    sVh[(lc + 1) * 264 + rr] = h1;
                    sVl[lc * 264 + rr] = __float2bfloat16(v0 - __bfloat162float(h0));
                    sVl[(lc + 1) * 264 + rr] = __float2bfloat16(v1 - __bfloat162float(h1));
                }
            }
        __syncthreads();
        for (int i = tid; i < 128 * 32; i += GTHREADS) {
            int row = i >> 5, seg = i & 31;
            int gn = bn + row;
            int hh = gn >> 6, dd = gn & 63;
            size_t dst = (size_t)(hh * DH + dd) * T_SEQ + bm + seg * 8;
            *(uint4*)(Ch + dst) = *(uint4*)(sVh + row * 264 + seg * 8);
            *(uint4*)(Cl + dst) = *(uint4*)(sVl + row * 264 + seg * 8);
        }
    }
}

// ---------------------------------------------------------------------------
// HMMA sliding-window attention (R4 structure; term-reordered MMA loops)
// ---------------------------------------------------------------------------
#define AROWB 176
#define ATILE (64 * AROWB)
#define ASTAGE (4 * ATILE)
#define ATTN_SMEM (2 * ASTAGE)
#define OFF_KH 0
#define OFF_KL ATILE
#define OFF_VH (2 * ATILE)
#define OFF_VL (3 * ATILE)

__device__ __forceinline__ void attn_load_tile(
    uint32_t base, const __nv_bfloat16* __restrict__ Kh,
    const __nv_bfloat16* __restrict__ Kl,
    const __nv_bfloat16* __restrict__ Vth,
    const __nv_bfloat16* __restrict__ Vtl,
    int h, int kt, int tid) {
#pragma unroll
    for (int i = 0; i < 4; i++) {
        int idx = tid + i * 128;
        int row = idx >> 3, seg = idx & 7;
        uint32_t dk = base + OFF_KH + row * AROWB + seg * 16;
        size_t ks = ((size_t)(h * T_SEQ + kt + row) << 6) + seg * 8;
        cp16(dk, Kh + ks);
        cp16(dk + ATILE, Kl + ks);
        uint32_t dv = base + OFF_VH + row * AROWB + seg * 16;
        size_t vs = (size_t)(h * DH + row) * T_SEQ + kt + seg * 8;
        cp16(dv, Vth + vs);
        cp16(dv + ATILE, Vtl + vs);
    }
    CP_COMMIT();
}

__global__ void __launch_bounds__(128)
attn_mma(const __nv_bfloat16* __restrict__ Qh, const __nv_bfloat16* __restrict__ Ql,
         const __nv_bfloat16* __restrict__ Kh, const __nv_bfloat16* __restrict__ Kl,
         const __nv_bfloat16* __restrict__ Vth, const __nv_bfloat16* __restrict__ Vtl,
         __nv_bfloat16* __restrict__ AOh, __nv_bfloat16* __restrict__ AOl) {
    extern __shared__ char smraw[];
    const uint32_t sb = smem_u32(smraw);
    const int tid = threadIdx.x;
    const int warp = tid >> 5;
    const int lane = tid & 31;
    const int h = blockIdx.y;
    const int q0 = blockIdx.x * 64;
    const int lrow = lane & 15;
    const int lseg = lane >> 4;

#pragma unroll
    for (int i = 0; i < 4; i++) {
        int idx = tid + i * 128;
        int row = idx >> 3, seg = idx & 7;
        uint32_t dst = sb + OFF_KH + row * AROWB + seg * 16;
        size_t qs = ((size_t)(h * T_SEQ + q0 + row) << 6) + seg * 8;
        cp16(dst, Qh + qs);
        cp16(dst + ATILE, Ql + qs);
    }
    CP_COMMIT();
    CP_WAIT(0);
    __syncthreads();

    uint32_t qfh[4][4], qfl[4][4];
#pragma unroll
    for (int k = 0; k < 4; k++) {
        uint32_t ad = sb + (warp * 16 + lrow) * AROWB + k * 32 + lseg * 16;
        ldsm4(qfh[k], ad);
        ldsm4(qfl[k], ad + ATILE);
    }
    __syncthreads();

    float o[8][4];
#pragma unroll
    for (int j = 0; j < 8; j++)
#pragma unroll
        for (int e = 0; e < 4; e++) o[j][e] = 0.0f;
    float m0 = -1e30f, m1 = -1e30f, l0 = 0.0f, l1 = 0.0f;

    const int kt_lo = (q0 >= WIN) ? (q0 - WIN) : 0;
    const int ntiles = (q0 - kt_lo) / 64 + 1;

    attn_load_tile(sb, Kh, Kl, Vth, Vtl, h, kt_lo, tid);
    if (ntiles > 1) attn_load_tile(sb + ASTAGE, Kh, Kl, Vth, Vtl, h, kt_lo + 64, tid);

    for (int ti = 0; ti < ntiles; ti++) {
        const int kt = kt_lo + ti * 64;
        const uint32_t base = sb + (uint32_t)(ti & 1) * ASTAGE;
        if (ti + 1 < ntiles) { CP_WAIT(1); } else { CP_WAIT(0); }
        __syncthreads();

        float sf[8][4];
#pragma unroll
        for (int j = 0; j < 8; j++)
#pragma unroll
            for (int e = 0; e < 4; e++) sf[j][e] = 0.0f;
#pragma unroll
        for (int kk = 0; kk < 4; kk++) {
            uint32_t bh[4][4], bl[4][4];
#pragma unroll
            for (int n16 = 0; n16 < 4; n16++) {
                uint32_t ad = base + OFF_KH + (n16 * 16 + lrow) * AROWB + kk * 32 + lseg * 16;
                ldsm4(bh[n16], ad);
                ldsm4(bl[n16], ad + ATILE);
            }
#pragma unroll
            for (int j = 0; j < 8; j++) {
                const int nh = j >> 1, sub = j & 1;
                mma16816(sf[j], qfh[kk], bh[nh][sub], bh[nh][sub + 2]);
            }
#pragma unroll
            for (int j = 0; j < 8; j++) {
                const int nh = j >> 1, sub = j & 1;
                mma16816(sf[j], qfh[kk], bl[nh][sub], bl[nh][sub + 2]);
            }
#pragma unroll
            for (int j = 0; j < 8; j++) {
                const int nh = j >> 1, sub = j & 1;
                mma16816(sf[j], qfl[kk], bh[nh][sub], bh[nh][sub + 2]);
            }
        }

        const int r0 = q0 + warp * 16 + (lane >> 2);
        const int r1 = r0 + 8;
#pragma unroll
        for (int j = 0; j < 8; j++) {
            const int c0 = kt + 8 * j + (lane & 3) * 2;
            const int c1 = c0 + 1;
            if (c0 > r0 || c0 < r0 - WIN) sf[j][0] = -1e30f;
            if (c1 > r0 || c1 < r0 - WIN) sf[j][1] = -1e30f;
            if (c0 > r1 || c0 < r1 - WIN) sf[j][2] = -1e30f;
            if (c1 > r1 || c1 < r1 - WIN) sf[j][3] = -1e30f;
        }

        float t0 = -1e30f, t1 = -1e30f;
#pragma unroll
        for (int j = 0; j < 8; j++) {
            t0 = fmaxf(t0, fmaxf(sf[j][0], sf[j][1]));
            t1 = fmaxf(t1, fmaxf(sf[j][2], sf[j][3]));
        }
        t0 = fmaxf(t0, __shfl_xor_sync(0xffffffffu, t0, 1));
        t0 = fmaxf(t0, __shfl_xor_sync(0xffffffffu, t0, 2));
        t1 = fmaxf(t1, __shfl_xor_sync(0xffffffffu, t1, 1));
        t1 = fmaxf(t1, __shfl_xor_sync(0xffffffffu, t1, 2));
        const float mn0 = fmaxf(m0, t0), mn1 = fmaxf(m1, t1);
        const float corr0 = __expf(m0 - mn0), corr1 = __expf(m1 - mn1);
        m0 = mn0;
        m1 = mn1;

        uint32_t ph[4][4], pl[4][4];
        float s0 = 0.0f, s1 = 0.0f;
#pragma unroll
        for (int j = 0; j < 8; j++) {
            float p0 = __expf(sf[j][0] - m0);
            float p1 = __expf(sf[j][1] - m0);
            float p2 = __expf(sf[j][2] - m1);
            float p3 = __expf(sf[j][3] - m1);
            s0 += p0 + p1;
            s1 += p2 + p3;
            __nv_bfloat16 b0 = __float2bfloat16(p0), b1 = __float2bfloat16(p1);
            __nv_bfloat16 b2 = __float2bfloat16(p2), b3 = __float2bfloat16(p3);
            const int kk = j >> 1, pos = (j & 1) * 2;
            ph[kk][pos + 0] = (uint32_t)__bfloat16_as_ushort(b0) |
                              ((uint32_t)__bfloat16_as_ushort(b1) << 16);
            ph[kk][pos + 1] = (uint32_t)__bfloat16_as_ushort(b2) |
                              ((uint32_t)__bfloat16_as_ushort(b3) << 16);
            pl[kk][pos + 0] = packbf(p0 - __bfloat162float(b0), p1 - __bfloat162float(b1));
            pl[kk][pos + 1] = packbf(p2 - __bfloat162float(b2), p3 - __bfloat162float(b3));
        }
        s0 += __shfl_xor_sync(0xffffffffu, s0, 1);
        s0 += __shfl_xor_sync(0xffffffffu, s0, 2);
        s1 += __shfl_xor_sync(0xffffffffu, s1, 1);
        s1 += __shfl_xor_sync(0xffffffffu, s1, 2);
        l0 = l0 * corr0 + s0;
        l1 = l1 * corr1 + s1;
#pragma unroll
        for (int j = 0; j < 8; j++) {
            o[j][0] *= corr0;
            o[j][1] *= corr0;
            o[j][2] *= corr1;
            o[j][3] *= corr1;
        }

#pragma unroll
        for (int kk = 0; kk < 4; kk++) {
            uint32_t vh[4][4], vl[4][4];
#pragma unroll
            for (int n16 = 0; n16 < 4; n16++) {
                uint32_t ad = base + OFF_VH + (n16 * 16 + lrow) * AROWB + kk * 32 + lseg * 16;
                ldsm4(vh[n16], ad);
                ldsm4(vl[n16], ad + ATILE);
            }
#pragma unroll
            for (int j = 0; j < 8; j++) {
                const int nh = j >> 1, sub = j & 1;
                mma16816(o[j], ph[kk], vh[nh][sub], vh[nh][sub + 2]);
            }
#pragma unroll
            for (int j = 0; j < 8; j++) {
                const int nh = j >> 1, sub = j & 1;
                mma16816(o[j], ph[kk], vl[nh][sub], vl[nh][sub + 2]);
            }
#pragma unroll
            for (int j = 0; j < 8; j++) {
                const int nh = j >> 1, sub = j & 1;
                mma16816(o[j], pl[kk], vh[nh][sub], vh[nh][sub + 2]);
            }
        }
        __syncthreads();
        if (ti + 2 < ntiles)
            attn_load_tile(sb + (uint32_t)(ti & 1) * ASTAGE, Kh, Kl, Vth, Vtl, h,
                           kt + 128, tid);
    }

    const float i0 = 1.0f / l0;
    const float i1 = 1.0f / l1;
    const int tr = q0 + warp * 16 + (lane >> 2);
#pragma unroll
    for (int j = 0; j < 8; j++) {
        const int d = 8 * j + (lane & 3) * 2;
        float v0 = o[j][0] * i0, v1 = o[j][1] * i0;
        float v2 = o[j][2] * i1, v3 = o[j][3] * i1;
        __nv_bfloat16 h0 = __float2bfloat16(v0), h1 = __float2bfloat16(v1);
        __nv_bfloat16 h2 = __float2bfloat16(v2), h3 = __float2bfloat16(v3);
        size_t a0 = (size_t)tr * DMODEL + h * DH + d;
        size_t a1 = (size_t)(tr + 8) * DMODEL + h * DH + d;
        *(uint32_t*)(AOh + a0) = (uint32_t)__bfloat16_as_ushort(h0) |
                                 ((uint32_t)__bfloat16_as_ushort(h1) << 16);
        *(uint32_t*)(AOh + a1) = (uint32_t)__bfloat16_as_ushort(h2) |
                                 ((uint32_t)__bfloat16_as_ushort(h3) << 16);
        *(uint32_t*)(AOl + a0) = packbf(v0 - __bfloat162float(h0), v1 - __bfloat162float(h1));
        *(uint32_t*)(AOl + a1) = packbf(v2 - __bfloat162float(h2), v3 - __bfloat162float(h3));
    }
}

// ---------------------------------------------------------------------------
extern "C" void kernel_launch(void* const* d_in, const int* in_sizes, int n_in,
                              void* d_out, int out_size) {
    const float* x  = (const float*)d_in[0];
    const float* Wq = (const float*)d_in[1];
    const float* Wk = (const float*)d_in[2];
    const float* Wv = (const float*)d_in[3];
    const float* Wo = (const float*)d_in[4];
    float* out = (float*)d_out;

    __nv_bfloat16 *pxh, *pxl, *pWh, *pWl, *paoh, *paol;
    __nv_bfloat16 *pQh, *pQl, *pKh, *pKl, *pVth, *pVtl;
    cudaGetSymbolAddress((void**)&pxh, g_xh);
    cudaGetSymbolAddress((void**)&pxl, g_xl);
    cudaGetSymbolAddress((void**)&pWh, g_Wh);
    cudaGetSymbolAddress((void**)&pWl, g_Wl);
    cudaGetSymbolAddress((void**)&paoh, g_aoh);
    cudaGetSymbolAddress((void**)&paol, g_aol);
    cudaGetSymbolAddress((void**)&pQh, g_Qh);
    cudaGetSymbolAddress((void**)&pQl, g_Ql);
    cudaGetSymbolAddress((void**)&pKh, g_Kh);
    cudaGetSymbolAddress((void**)&pKl, g_Kl);
    cudaGetSymbolAddress((void**)&pVth, g_Vth);
    cudaGetSymbolAddress((void**)&pVtl, g_Vtl);

    cudaFuncSetAttribute(gemm_mma<0>, cudaFuncAttributeMaxDynamicSharedMemorySize, GEMM_SMEM);
    cudaFuncSetAttribute(gemm_mma<1>, cudaFuncAttributeMaxDynamicSharedMemorySize, GEMM_SMEM);
    cudaFuncSetAttribute(gemm_mma<2>, cudaFuncAttributeMaxDynamicSharedMemorySize, GEMM_SMEM);
    cudaFuncSetAttribute(attn_mma, cudaFuncAttributeMaxDynamicSharedMemorySize, ATTN_SMEM);

    const int n4x = T_SEQ * DMODEL / 4;
    const int n4w = DMODEL * DMODEL / 4;
    const int WSZ = DMODEL * DMODEL;

    splitk<<<n4x / 256, 256>>>(x, pxh, pxl, n4x);
    dim3 wgrid(n4w / 256, 4);
    splitW<<<wgrid, 256>>>(Wq, Wk, Wv, Wo, pWh, pWl);

    dim3 ggrid(DMODEL / 128, T_SEQ / 256);  // (8, 16) = 128 CTAs, one wave
    gemm_mma<1><<<ggrid, GTHREADS, GEMM_SMEM>>>(pxh, pxl, pWh + 0 * WSZ, pWl + 0 * WSZ,
                                                nullptr, pQh, pQl, 0.125f);
    gemm_mma<1><<<ggrid, GTHREADS, GEMM_SMEM>>>(pxh, pxl, pWh + 1 * WSZ, pWl + 1 * WSZ,
                                                nullptr, pKh, pKl, 1.0f);
    gemm_mma<2><<<ggrid, GTHREADS, GEMM_SMEM>>>(pxh, pxl, pWh + 2 * WSZ, pWl + 2 * WSZ,
                                                nullptr, pVth, pVtl, 1.0f);

    dim3 agrid(T_SEQ / 64, NHEADS);  // (64, 16)
    attn_mma<<<agrid, 128, ATTN_SMEM>>>(pQh, pQl, pKh, pKl, pVth, pVtl, paoh, paol);

    gemm_mma<0><<<ggrid, GTHREADS, GEMM_SMEM>>>(paoh, paol, pWh + 3 * WSZ, pWl + 3 * WSZ,
                                                out, nullptr, nullptr, 1.0f);
}

// round 7
// speedup vs baseline: 3.3895x; 1.4222x over previous
#include <cuda_runtime.h>
#include <cuda_fp16.h>
#include <cstdint>
#include <math.h>

#define T_SEQ 4096
#define DMODEL 1024
#define NHEADS 16
#define DH 64
#define WIN 256

// ---------------------------------------------------------------------------
// Scratch (__device__ globals; allocation-free rule). All fp16.
// ---------------------------------------------------------------------------
__device__ __align__(16) __half g_x16[T_SEQ * DMODEL];
__device__ __align__(16) __half g_Wh[4 * DMODEL * DMODEL];
__device__ __align__(16) __half g_Wl[4 * DMODEL * DMODEL];
__device__ __align__(16) __half g_ao16[T_SEQ * DMODEL];
__device__ __align__(16) __half g_Q16[NHEADS * T_SEQ * DH];   // [h][t][d], prescaled
__device__ __align__(16) __half g_Kh[NHEADS * T_SEQ * DH];
__device__ __align__(16) __half g_Kl[NHEADS * T_SEQ * DH];
__device__ __align__(16) __half g_Vth[NHEADS * DH * T_SEQ];   // [h][d][t]
__device__ __align__(16) __half g_Vtl[NHEADS * DH * T_SEQ];

// ---------------------------------------------------------------------------
// PTX helpers (generic PTX only)
// ---------------------------------------------------------------------------
__device__ __forceinline__ uint32_t smem_u32(const void* p) {
    uint32_t a;
    asm("{ .reg .u64 t; cvta.to.shared.u64 t, %1; cvt.u32.u64 %0, t; }"
        : "=r"(a) : "l"(p));
    return a;
}

__device__ __forceinline__ void cp16(uint32_t dst, const void* src) {
    asm volatile("cp.async.cg.shared.global [%0], [%1], 16;" :: "r"(dst), "l"(src));
}
#define CP_COMMIT() asm volatile("cp.async.commit_group;" ::: "memory")
#define CP_WAIT(n)  asm volatile("cp.async.wait_group %0;" :: "n"(n) : "memory")

__device__ __forceinline__ void ldsm4(uint32_t (&r)[4], uint32_t addr) {
    asm volatile("ldmatrix.sync.aligned.m8n8.x4.shared.b16 {%0,%1,%2,%3}, [%4];"
                 : "=r"(r[0]), "=r"(r[1]), "=r"(r[2]), "=r"(r[3]) : "r"(addr));
}

// fp16 HMMA m16n8k16, fp32 accumulate
__device__ __forceinline__ void mmah(float (&d)[4], const uint32_t (&a)[4],
                                     uint32_t b0, uint32_t b1) {
    asm volatile(
        "mma.sync.aligned.m16n8k16.row.col.f32.f16.f16.f32 "
        "{%0,%1,%2,%3}, {%4,%5,%6,%7}, {%8,%9}, {%0,%1,%2,%3};"
        : "+f"(d[0]), "+f"(d[1]), "+f"(d[2]), "+f"(d[3])
        : "r"(a[0]), "r"(a[1]), "r"(a[2]), "r"(a[3]), "r"(b0), "r"(b1));
}

__device__ __forceinline__ uint32_t packh(float x, float y) {
    __half hx = __float2half_rn(x), hy = __float2half_rn(y);
    return (uint32_t)__half_as_ushort(hx) | ((uint32_t)__half_as_ushort(hy) << 16);
}

// ---------------------------------------------------------------------------
// fp32 -> fp16 conversions
// ---------------------------------------------------------------------------
__global__ void convX(const float* __restrict__ in, __half* __restrict__ out, int n4) {
    int i = blockIdx.x * 256 + threadIdx.x;
    if (i >= n4) return;
    float4 v = ((const float4*)in)[i];
    uint2 o;
    o.x = packh(v.x, v.y);
    o.y = packh(v.z, v.w);
    ((uint2*)out)[i] = o;
}

__global__ void splitW(const float* __restrict__ W0, const float* __restrict__ W1,
                       const float* __restrict__ W2, const float* __restrict__ W3,
                       __half* __restrict__ hi, __half* __restrict__ lo) {
    const int w = blockIdx.y;
    const float* src = (w == 0) ? W0 : (w == 1) ? W1 : (w == 2) ? W2 : W3;
    const int WSZ = DMODEL * DMODEL;
    int i = blockIdx.x * 256 + threadIdx.x;
    float4 v = ((const float4*)src)[i];
    float f[4] = {v.x, v.y, v.z, v.w};
    unsigned short h[4], l[4];
#pragma unroll
    for (int j = 0; j < 4; j++) {
        __half hb = __float2half_rn(f[j]);
        __half lb = __float2half_rn(f[j] - __half2float(hb));
        h[j] = __half_as_ushort(hb);
        l[j] = __half_as_ushort(lb);
    }
    uint2 uh, ul;
    uh.x = (uint32_t)h[0] | ((uint32_t)h[1] << 16);
    uh.y = (uint32_t)h[2] | ((uint32_t)h[3] << 16);
    ul.x = (uint32_t)l[0] | ((uint32_t)l[1] << 16);
    ul.y = (uint32_t)l[2] | ((uint32_t)l[3] << 16);
    ((uint2*)(hi + (size_t)w * WSZ))[i] = uh;
    ((uint2*)(lo + (size_t)w * WSZ))[i] = ul;
}

// ---------------------------------------------------------------------------
// fp16 2-term GEMM: C[m,n] = sum_k A[m,k]*(Bh+Bl)[n,k]
// CTA 128x128, 256 thr / 8 warps (warp tile 64x32), KC=32, 3-stage cp.async,
// 2 CTAs/SM. EPI 0: fp32 row-major. EPI 1: fp16 single head-major (*scale).
// EPI 2: fp16 hi/lo head-major. EPI 3: fp16 hi/lo transposed [h][d][t].
// ---------------------------------------------------------------------------
#define KC 32
#define ROWB 80
#define TROWS 128
#define TILE_B (TROWS * ROWB)            // 10240
#define OFF_A 0
#define OFF_BH TILE_B
#define OFF_BL (2 * TILE_B)
#define STAGE_B (3 * TILE_B)             // 30720
#define NSTAGE 3
#define GEMM_SMEM (NSTAGE * STAGE_B)     // 92160
#define NCH (DMODEL / KC)                // 32

__device__ __forceinline__ void gemm_issue(
    uint32_t sb, int stage, int chunk,
    const __half* __restrict__ A, const __half* __restrict__ Bh,
    const __half* __restrict__ Bl, int bm, int bn, int tid) {
    const uint32_t st = sb + (uint32_t)stage * STAGE_B;
    const __half* aA = A + (size_t)bm * DMODEL;
    const __half* bH = Bh + (size_t)bn * DMODEL;
    const __half* bL = Bl + (size_t)bn * DMODEL;
#pragma unroll
    for (int i = 0; i < 2; i++) {
        int slot = tid + i * 256;
        int row = slot >> 2, seg = slot & 3;
        uint32_t off = row * ROWB + seg * 16;
        const size_t g = (size_t)row * DMODEL + chunk * KC + seg * 8;
        cp16(st + OFF_A + off, aA + g);
        cp16(st + OFF_BH + off, bH + g);
        cp16(st + OFF_BL + off, bL + g);
    }
    CP_COMMIT();
}

template <int EPI>
__global__ void __launch_bounds__(256, 2)
gemm_mma(const __half* __restrict__ A, const __half* __restrict__ Bh,
         const __half* __restrict__ Bl, float* __restrict__ Cf,
         __half* __restrict__ Ch, __half* __restrict__ Cl, float scale) {
    extern __shared__ char smraw[];
    const uint32_t sb = smem_u32(smraw);

    const int tid = threadIdx.x;
    const int warp = tid >> 5;
    const int lane = tid & 31;
    const int bm = blockIdx.y * 128;
    const int bn = blockIdx.x * 128;
    const int wm = (warp >> 2) * 64;   // 0,64
    const int wn = (warp & 3) * 32;    // 0,32,64,96

    float acc[4][4][4];
#pragma unroll
    for (int i = 0; i < 4; i++)
#pragma unroll
        for (int j = 0; j < 4; j++)
#pragma unroll
            for (int e = 0; e < 4; e++) acc[i][j][e] = 0.0f;

    const int lrow = lane & 15;
    const int lseg = lane >> 4;

    gemm_issue(sb, 0, 0, A, Bh, Bl, bm, bn, tid);
    gemm_issue(sb, 1, 1, A, Bh, Bl, bm, bn, tid);
    gemm_issue(sb, 2, 2, A, Bh, Bl, bm, bn, tid);

    int stage = 0;
    for (int c = 0; c < NCH; c++) {
        if (c <= NCH - 3) { CP_WAIT(2); }
        else if (c == NCH - 2) { CP_WAIT(1); }
        else { CP_WAIT(0); }
        __syncthreads();

        const uint32_t st = sb + (uint32_t)stage * STAGE_B;
#pragma unroll
        for (int kk = 0; kk < 2; kk++) {
            uint32_t af[4][4];
            uint32_t bh[2][4], bl[2][4];
#pragma unroll
            for (int mi = 0; mi < 4; mi++) {
                uint32_t ad = st + OFF_A + (wm + mi * 16 + lrow) * ROWB + kk * 32 + lseg * 16;
                ldsm4(af[mi], ad);
            }
#pragma unroll
            for (int n16 = 0; n16 < 2; n16++) {
                uint32_t ad = st + (wn + n16 * 16 + lrow) * ROWB + kk * 32 + lseg * 16;
                ldsm4(bh[n16], ad + OFF_BH);
                ldsm4(bl[n16], ad + OFF_BL);
            }
#pragma unroll
            for (int mi = 0; mi < 4; mi++)
#pragma unroll
                for (int nj = 0; nj < 4; nj++) {
                    const int nh = nj >> 1, sub = nj & 1;
                    mmah(acc[mi][nj], af[mi], bh[nh][sub], bh[nh][sub + 2]);
                }
#pragma unroll
            for (int mi = 0; mi < 4; mi++)
#pragma unroll
                for (int nj = 0; nj < 4; nj++) {
                    const int nh = nj >> 1, sub = nj & 1;
                    mmah(acc[mi][nj], af[mi], bl[nh][sub], bl[nh][sub + 2]);
                }
        }
        __syncthreads();
        if (c + 3 < NCH)
            gemm_issue(sb, stage, c + 3, A, Bh, Bl, bm, bn, tid);
        stage = (stage == 2) ? 0 : stage + 1;
    }

    const int r0 = bm + wm + (lane >> 2);
    const int c0 = bn + wn + (lane & 3) * 2;

    if (EPI == 0) {
#pragma unroll
        for (int mi = 0; mi < 4; mi++)
#pragma unroll
            for (int nj = 0; nj < 4; nj++) {
                const int r = r0 + mi * 16;
                const int cc = c0 + nj * 8;
                float* d0 = Cf + (size_t)r * DMODEL + cc;
                float* d1 = Cf + (size_t)(r + 8) * DMODEL + cc;
                *(float2*)d0 = make_float2(acc[mi][nj][0], acc[mi][nj][1]);
                *(float2*)d1 = make_float2(acc[mi][nj][2], acc[mi][nj][3]);
            }
    } else if (EPI == 1) {
#pragma unroll
        for (int mi = 0; mi < 4; mi++)
#pragma unroll
            for (int nj = 0; nj < 4; nj++) {
                const int r = r0 + mi * 16;
                const int cc = c0 + nj * 8;
                const int h = cc >> 6;
                const int cl = cc & 63;
#pragma unroll
                for (int half = 0; half < 2; half++) {
                    float v0 = acc[mi][nj][half * 2 + 0] * scale;
                    float v1 = acc[mi][nj][half * 2 + 1] * scale;
                    size_t base = ((size_t)(h * T_SEQ + r + half * 8) << 6) + cl;
                    *(uint32_t*)(Ch + base) = packh(v0, v1);
                }
            }
    } else if (EPI == 2) {
#pragma unroll
        for (int mi = 0; mi < 4; mi++)
#pragma unroll
            for (int nj = 0; nj < 4; nj++) {
                const int r = r0 + mi * 16;
                const int cc = c0 + nj * 8;
                const int h = cc >> 6;
                const int cl = cc & 63;
#pragma unroll
                for (int half = 0; half < 2; half++) {
                    float v0 = acc[mi][nj][half * 2 + 0];
                    float v1 = acc[mi][nj][half * 2 + 1];
                    __half h0 = __float2half_rn(v0);
                    __half h1 = __float2half_rn(v1);
                    size_t base = ((size_t)(h * T_SEQ + r + half * 8) << 6) + cl;
                    *(uint32_t*)(Ch + base) =
                        (uint32_t)__half_as_ushort(h0) |
                        ((uint32_t)__half_as_ushort(h1) << 16);
                    *(uint32_t*)(Cl + base) =
                        packh(v0 - __half2float(h0), v1 - __half2float(h1));
                }
            }
    } else {
        // EPI 3: transpose to [h][d][t] via smem staging (reuse pipeline smem)
        __syncthreads();
        __half* sVh = (__half*)smraw;          // [128 n][136 m-pad]
        __half* sVl = sVh + 128 * 136;
        const int lr0 = wm + (lane >> 2);
        const int lc0 = wn + (lane & 3) * 2;
#pragma unroll
        for (int mi = 0; mi < 4; mi++)
#pragma unroll
            for (int nj = 0; nj < 4; nj++) {
                const int lc = lc0 + nj * 8;
#pragma unroll
                for (int half = 0; half < 2; half++) {
                    float v0 = acc[mi][nj][half * 2 + 0];
                    float v1 = acc[mi][nj][half * 2 + 1];
                    __half h0 = __float2half_rn(v0);
                    __half h1 = __float2half_rn(v1);
                    int rr = lr0 + mi * 16 + half * 8;
                    sVh[lc * 136 + rr] = h0;
                    sVh[(lc + 1) * 136 + rr] = h1;
                    sVl[lc * 136 + rr] = __float2half_rn(v0 - __half2float(h0));
                    sVl[(lc + 1) * 136 + rr] = __float2half_rn(v1 - __half2float(h1));
                }
            }
        __syncthreads();
        for (int i = tid; i < 128 * 16; i += 256) {
            int row = i >> 4, seg = i & 15;
            int gn = bn + row;
            int hh = gn >> 6, dd = gn & 63;
            size_t dst = (size_t)(hh * DH + dd) * T_SEQ + bm + seg * 8;
            *(uint4*)(Ch + dst) = *(uint4*)(sVh + row * 136 + seg * 8);
            *(uint4*)(Cl + dst) = *(uint4*)(sVl + row * 136 + seg * 8);
        }
    }
}

// ---------------------------------------------------------------------------
// fp16 HMMA sliding-window attention: Q single, K hi/lo, V hi/lo, P single.
// CTA = (64-query tile, head), 4 warps.
// ---------------------------------------------------------------------------
#define AROWB 176
#define ATILE (64 * AROWB)
#define ASTAGE (4 * ATILE)
#define ATTN_SMEM (2 * ASTAGE)
#define OFF_KH 0
#define OFF_KL ATILE
#define OFF_VH (2 * ATILE)
#define OFF_VL (3 * ATILE)

__device__ __forceinline__ void attn_load_tile(
    uint32_t base, const __half* __restrict__ Kh, const __half* __restrict__ Kl,
    const __half* __restrict__ Vth, const __half* __restrict__ Vtl,
    int h, int kt, int tid) {
#pragma unroll
    for (int i = 0; i < 4; i++) {
        int idx = tid + i * 128;
        int row = idx >> 3, seg = idx & 7;
        uint32_t dk = base + OFF_KH + row * AROWB + seg * 16;
        size_t ks = ((size_t)(h * T_SEQ + kt + row) << 6) + seg * 8;
        cp16(dk, Kh + ks);
        cp16(dk + ATILE, Kl + ks);
        uint32_t dv = base + OFF_VH + row * AROWB + seg * 16;
        size_t vs = (size_t)(h * DH + row) * T_SEQ + kt + seg * 8;
        cp16(dv, Vth + vs);
        cp16(dv + ATILE, Vtl + vs);
    }
    CP_COMMIT();
}

__global__ void __launch_bounds__(128)
attn_mma(const __half* __restrict__ Q16,
         const __half* __restrict__ Kh, const __half* __restrict__ Kl,
         const __half* __restrict__ Vth, const __half* __restrict__ Vtl,
         __half* __restrict__ AO) {
    extern __shared__ char smraw[];
    const uint32_t sb = smem_u32(smraw);
    const int tid = threadIdx.x;
    const int warp = tid >> 5;
    const int lane = tid & 31;
    const int h = blockIdx.y;
    const int q0 = blockIdx.x * 64;
    const int lrow = lane & 15;
    const int lseg = lane >> 4;

    // stage Q (prescaled) into stage0 KH slot
#pragma unroll
    for (int i = 0; i < 4; i++) {
        int idx = tid + i * 128;
        int row = idx >> 3, seg = idx & 7;
        uint32_t dst = sb + OFF_KH + row * AROWB + seg * 16;
        size_t qs = ((size_t)(h * T_SEQ + q0 + row) << 6) + seg * 8;
        cp16(dst, Q16 + qs);
    }
    CP_COMMIT();
    CP_WAIT(0);
    __syncthreads();

    uint32_t qf[4][4];
#pragma unroll
    for (int k = 0; k < 4; k++) {
        uint32_t ad = sb + (warp * 16 + lrow) * AROWB + k * 32 + lseg * 16;
        ldsm4(qf[k], ad);
    }
    __syncthreads();

    float o[8][4];
#pragma unroll
    for (int j = 0; j < 8; j++)
#pragma unroll
        for (int e = 0; e < 4; e++) o[j][e] = 0.0f;
    float m0 = -1e30f, m1 = -1e30f, l0 = 0.0f, l1 = 0.0f;

    const int kt_lo = (q0 >= WIN) ? (q0 - WIN) : 0;
    const int ntiles = (q0 - kt_lo) / 64 + 1;

    attn_load_tile(sb, Kh, Kl, Vth, Vtl, h, kt_lo, tid);
    if (ntiles > 1) attn_load_tile(sb + ASTAGE, Kh, Kl, Vth, Vtl, h, kt_lo + 64, tid);

    for (int ti = 0; ti < ntiles; ti++) {
        const int kt = kt_lo + ti * 64;
        const uint32_t base = sb + (uint32_t)(ti & 1) * ASTAGE;
        if (ti + 1 < ntiles) { CP_WAIT(1); } else { CP_WAIT(0); }
        __syncthreads();

        // ---- S = Q K^T (2-term) ----
        float sf[8][4];
#pragma unroll
        for (int j = 0; j < 8; j++)
#pragma unroll
            for (int e = 0; e < 4; e++) sf[j][e] = 0.0f;
#pragma unroll
        for (int kk = 0; kk < 4; kk++) {
            uint32_t bh[4][4], bl[4][4];
#pragma unroll
            for (int n16 = 0; n16 < 4; n16++) {
                uint32_t ad = base + (n16 * 16 + lrow) * AROWB + kk * 32 + lseg * 16;
                ldsm4(bh[n16], ad + OFF_KH);
                ldsm4(bl[n16], ad + OFF_KL);
            }
#pragma unroll
            for (int j = 0; j < 8; j++) {
                const int nh = j >> 1, sub = j & 1;
                mmah(sf[j], qf[kk], bh[nh][sub], bh[nh][sub + 2]);
            }
#pragma unroll
            for (int j = 0; j < 8; j++) {
                const int nh = j >> 1, sub = j & 1;
                mmah(sf[j], qf[kk], bl[nh][sub], bl[nh][sub + 2]);
            }
        }

        // ---- mask ----
        const int r0 = q0 + warp * 16 + (lane >> 2);
        const int r1 = r0 + 8;
#pragma unroll
        for (int j = 0; j < 8; j++) {
            const int c0 = kt + 8 * j + (lane & 3) * 2;
            const int c1 = c0 + 1;
            if (c0 > r0 || c0 < r0 - WIN) sf[j][0] = -1e30f;
            if (c1 > r0 || c1 < r0 - WIN) sf[j][1] = -1e30f;
            if (c0 > r1 || c0 < r1 - WIN) sf[j][2] = -1e30f;
            if (c1 > r1 || c1 < r1 - WIN) sf[j][3] = -1e30f;
        }

        // ---- online softmax ----
        float t0 = -1e30f, t1 = -1e30f;
#pragma unroll
        for (int j = 0; j < 8; j++) {
            t0 = fmaxf(t0, fmaxf(sf[j][0], sf[j][1]));
            t1 = fmaxf(t1, fmaxf(sf[j][2], sf[j][3]));
        }
        t0 = fmaxf(t0, __shfl_xor_sync(0xffffffffu, t0, 1));
        t0 = fmaxf(t0, __shfl_xor_sync(0xffffffffu, t0, 2));
        t1 = fmaxf(t1, __shfl_xor_sync(0xffffffffu, t1, 1));
        t1 = fmaxf(t1, __shfl_xor_sync(0xffffffffu, t1, 2));
        const float mn0 = fmaxf(m0, t0), mn1 = fmaxf(m1, t1);
        const float corr0 = __expf(m0 - mn0), corr1 = __expf(m1 - mn1);
        m0 = mn0;
        m1 = mn1;

        uint32_t ph[4][4];
        float s0 = 0.0f, s1 = 0.0f;
#pragma unroll
        for (int j = 0; j < 8; j++) {
            float p0 = __expf(sf[j][0] - m0);
            float p1 = __expf(sf[j][1] - m0);
            float p2 = __expf(sf[j][2] - m1);
            float p3 = __expf(sf[j][3] - m1);
            s0 += p0 + p1;
            s1 += p2 + p3;
            const int kk = j >> 1, pos = (j & 1) * 2;
            ph[kk][pos + 0] = packh(p0, p1);
            ph[kk][pos + 1] = packh(p2, p3);
        }
        s0 += __shfl_xor_sync(0xffffffffu, s0, 1);
        s0 += __shfl_xor_sync(0xffffffffu, s0, 2);
        s1 += __shfl_xor_sync(0xffffffffu, s1, 1);
        s1 += __shfl_xor_sync(0xffffffffu, s1, 2);
        l0 = l0 * corr0 + s0;
        l1 = l1 * corr1 + s1;
#pragma unroll
        for (int j = 0; j < 8; j++) {
            o[j][0] *= corr0;
            o[j][1] *= corr0;
            o[j][2] *= corr1;
            o[j][3] *= corr1;
        }

        // ---- O += P V (2-term) ----
#pragma unroll
        for (int kk = 0; kk < 4; kk++) {
            uint32_t vh[4][4], vl[4][4];
#pragma unroll
            for (int n16 = 0; n16 < 4; n16++) {
                uint32_t ad = base + (n16 * 16 + lrow) * AROWB + kk * 32 + lseg * 16;
                ldsm4(vh[n16], ad + OFF_VH);
                ldsm4(vl[n16], ad + OFF_VL);
            }
#pragma unroll
            for (int j = 0; j < 8; j++) {
                const int nh = j >> 1, sub = j & 1;
                mmah(o[j], ph[kk], vh[nh][sub], vh[nh][sub + 2]);
            }
#pragma unroll
            for (int j = 0; j < 8; j++) {
                const int nh = j >> 1, sub = j & 1;
                mmah(o[j], ph[kk], vl[nh][sub], vl[nh][sub + 2]);
            }
        }
        __syncthreads();
        if (ti + 2 < ntiles)
            attn_load_tile(sb + (uint32_t)(ti & 1) * ASTAGE, Kh, Kl, Vth, Vtl, h,
                           kt + 128, tid);
    }

    // ---- epilogue: O/l -> fp16 AO [t][h*64+d] ----
    const float i0 = 1.0f / l0;
    const float i1 = 1.0f / l1;
    const int tr = q0 + warp * 16 + (lane >> 2);
#pragma unroll
    for (int j = 0; j < 8; j++) {
        const int d = 8 * j + (lane & 3) * 2;
        size_t a0 = (size_t)tr * DMODEL + h * DH + d;
        size_t a1 = (size_t)(tr + 8) * DMODEL + h * DH + d;
        *(uint32_t*)(AO + a0) = packh(o[j][0] * i0, o[j][1] * i0);
        *(uint32_t*)(AO + a1) = packh(o[j][2] * i1, o[j][3] * i1);
    }
}

// ---------------------------------------------------------------------------
extern "C" void kernel_launch(void* const* d_in, const int* in_sizes, int n_in,
                              void* d_out, int out_size) {
    const float* x  = (const float*)d_in[0];
    const float* Wq = (const float*)d_in[1];
    const float* Wk = (const float*)d_in[2];
    const float* Wv = (const float*)d_in[3];
    const float* Wo = (const float*)d_in[4];
    float* out = (float*)d_out;

    __half *px16, *pWh, *pWl, *pao16, *pQ16, *pKh, *pKl, *pVth, *pVtl;
    cudaGetSymbolAddress((void**)&px16, g_x16);
    cudaGetSymbolAddress((void**)&pWh, g_Wh);
    cudaGetSymbolAddress((void**)&pWl, g_Wl);
    cudaGetSymbolAddress((void**)&pao16, g_ao16);
    cudaGetSymbolAddress((void**)&pQ16, g_Q16);
    cudaGetSymbolAddress((void**)&pKh, g_Kh);
    cudaGetSymbolAddress((void**)&pKl, g_Kl);
    cudaGetSymbolAddress((void**)&pVth, g_Vth);
    cudaGetSymbolAddress((void**)&pVtl, g_Vtl);

    cudaFuncSetAttribute(gemm_mma<0>, cudaFuncAttributeMaxDynamicSharedMemorySize, GEMM_SMEM);
    cudaFuncSetAttribute(gemm_mma<1>, cudaFuncAttributeMaxDynamicSharedMemorySize, GEMM_SMEM);
    cudaFuncSetAttribute(gemm_mma<2>, cudaFuncAttributeMaxDynamicSharedMemorySize, GEMM_SMEM);
    cudaFuncSetAttribute(gemm_mma<3>, cudaFuncAttributeMaxDynamicSharedMemorySize, GEMM_SMEM);
    cudaFuncSetAttribute(attn_mma, cudaFuncAttributeMaxDynamicSharedMemorySize, ATTN_SMEM);

    const int n4x = T_SEQ * DMODEL / 4;
    const int n4w = DMODEL * DMODEL / 4;
    const int WSZ = DMODEL * DMODEL;

    convX<<<n4x / 256, 256>>>(x, px16, n4x);
    dim3 wgrid(n4w / 256, 4);
    splitW<<<wgrid, 256>>>(Wq, Wk, Wv, Wo, pWh, pWl);

    dim3 ggrid(DMODEL / 128, T_SEQ / 128);  // (8, 32) = 256 CTAs, 2/SM
    gemm_mma<1><<<ggrid, 256, GEMM_SMEM>>>(px16, pWh + 0 * WSZ, pWl + 0 * WSZ,
                                           nullptr, pQ16, nullptr, 0.125f);
    gemm_mma<2><<<ggrid, 256, GEMM_SMEM>>>(px16, pWh + 1 * WSZ, pWl + 1 * WSZ,
                                           nullptr, pKh, pKl, 1.0f);
    gemm_mma<3><<<ggrid, 256, GEMM_SMEM>>>(px16, pWh + 2 * WSZ, pWl + 2 * WSZ,
                                           nullptr, pVth, pVtl, 1.0f);

    dim3 agrid(T_SEQ / 64, NHEADS);  // (64, 16)
    attn_mma<<<agrid, 128, ATTN_SMEM>>>(pQ16, pKh, pKl, pVth, pVtl, pao16);

    gemm_mma<0><<<ggrid, 256, GEMM_SMEM>>>(pao16, pWh + 3 * WSZ, pWl + 3 * WSZ,
                                           out, nullptr, nullptr, 1.0f);
}

// round 8
// speedup vs baseline: 5.6753x; 1.6744x over previous
#include <cuda_runtime.h>
#include <cuda_fp16.h>
#include <cstdint>
#include <math.h>

#define T_SEQ 4096
#define DMODEL 1024
#define NHEADS 16
#define DH 64
#define WIN 256

// ---------------------------------------------------------------------------
// Scratch (__device__ globals; allocation-free rule). All fp16, single copy.
// ---------------------------------------------------------------------------
__device__ __align__(16) __half g_x16[T_SEQ * DMODEL];
__device__ __align__(16) __half g_W16[4 * DMODEL * DMODEL];
__device__ __align__(16) __half g_ao16[T_SEQ * DMODEL];
__device__ __align__(16) __half g_Q16[NHEADS * T_SEQ * DH];   // [h][t][d], prescaled
__device__ __align__(16) __half g_K16[NHEADS * T_SEQ * DH];   // [h][t][d]
__device__ __align__(16) __half g_Vt16[NHEADS * DH * T_SEQ];  // [h][d][t]

// ---------------------------------------------------------------------------
// PTX helpers (generic PTX only)
// ---------------------------------------------------------------------------
__device__ __forceinline__ uint32_t smem_u32(const void* p) {
    uint32_t a;
    asm("{ .reg .u64 t; cvta.to.shared.u64 t, %1; cvt.u32.u64 %0, t; }"
        : "=r"(a) : "l"(p));
    return a;
}

__device__ __forceinline__ void cp16(uint32_t dst, const void* src) {
    asm volatile("cp.async.cg.shared.global [%0], [%1], 16;" :: "r"(dst), "l"(src));
}
#define CP_COMMIT() asm volatile("cp.async.commit_group;" ::: "memory")
#define CP_WAIT(n)  asm volatile("cp.async.wait_group %0;" :: "n"(n) : "memory")

__device__ __forceinline__ void ldsm4(uint32_t (&r)[4], uint32_t addr) {
    asm volatile("ldmatrix.sync.aligned.m8n8.x4.shared.b16 {%0,%1,%2,%3}, [%4];"
                 : "=r"(r[0]), "=r"(r[1]), "=r"(r[2]), "=r"(r[3]) : "r"(addr));
}

__device__ __forceinline__ void mmah(float (&d)[4], const uint32_t (&a)[4],
                                     uint32_t b0, uint32_t b1) {
    asm volatile(
        "mma.sync.aligned.m16n8k16.row.col.f32.f16.f16.f32 "
        "{%0,%1,%2,%3}, {%4,%5,%6,%7}, {%8,%9}, {%0,%1,%2,%3};"
        : "+f"(d[0]), "+f"(d[1]), "+f"(d[2]), "+f"(d[3])
        : "r"(a[0]), "r"(a[1]), "r"(a[2]), "r"(a[3]), "r"(b0), "r"(b1));
}

__device__ __forceinline__ uint32_t packh(float x, float y) {
    __half hx = __float2half_rn(x), hy = __float2half_rn(y);
    return (uint32_t)__half_as_ushort(hx) | ((uint32_t)__half_as_ushort(hy) << 16);
}

// ---------------------------------------------------------------------------
// fp32 -> fp16 conversions
// ---------------------------------------------------------------------------
__global__ void convX(const float* __restrict__ in, __half* __restrict__ out, int n4) {
    int i = blockIdx.x * 256 + threadIdx.x;
    if (i >= n4) return;
    float4 v = ((const float4*)in)[i];
    uint2 o;
    o.x = packh(v.x, v.y);
    o.y = packh(v.z, v.w);
    ((uint2*)out)[i] = o;
}

__global__ void convW(const float* __restrict__ W0, const float* __restrict__ W1,
                      const float* __restrict__ W2, const float* __restrict__ W3,
                      __half* __restrict__ out) {
    const int w = blockIdx.y;
    const float* src = (w == 0) ? W0 : (w == 1) ? W1 : (w == 2) ? W2 : W3;
    const int WSZ = DMODEL * DMODEL;
    int i = blockIdx.x * 256 + threadIdx.x;
    float4 v = ((const float4*)src)[i];
    uint2 o;
    o.x = packh(v.x, v.y);
    o.y = packh(v.z, v.w);
    ((uint2*)(out + (size_t)w * WSZ))[i] = o;
}

// ---------------------------------------------------------------------------
// fp16 single-term GEMM: C[m,n] = sum_k A[m,k]*B[n,k]
// CTA 128x128, 256 thr / 8 warps (warp tile 64x32), KC=32, 3-stage cp.async,
// 2 CTAs/SM. EPI 0: fp32 row-major. EPI 1: fp16 head-major [h][t][d] (*scale).
// EPI 2: fp16 transposed [h][d][t] via smem staging.
// ---------------------------------------------------------------------------
#define KC 32
#define ROWB 80
#define TILE_B (128 * ROWB)              // 10240
#define OFF_A 0
#define OFF_B TILE_B
#define STAGE_B (2 * TILE_B)             // 20480
#define NSTAGE 3
#define GEMM_SMEM (NSTAGE * STAGE_B)     // 61440
#define NCH (DMODEL / KC)                // 32

__device__ __forceinline__ void gemm_issue(
    uint32_t sb, int stage, int chunk,
    const __half* __restrict__ A, const __half* __restrict__ B,
    int bm, int bn, int tid) {
    const uint32_t st = sb + (uint32_t)stage * STAGE_B;
    const __half* aA = A + (size_t)bm * DMODEL;
    const __half* bB = B + (size_t)bn * DMODEL;
#pragma unroll
    for (int i = 0; i < 2; i++) {
        int slot = tid + i * 256;
        int row = slot >> 2, seg = slot & 3;
        uint32_t off = row * ROWB + seg * 16;
        const size_t g = (size_t)row * DMODEL + chunk * KC + seg * 8;
        cp16(st + OFF_A + off, aA + g);
        cp16(st + OFF_B + off, bB + g);
    }
    CP_COMMIT();
}

template <int EPI>
__global__ void __launch_bounds__(256, 2)
gemm_mma(const __half* __restrict__ A, const __half* __restrict__ B,
         float* __restrict__ Cf, __half* __restrict__ Ch, float scale) {
    extern __shared__ char smraw[];
    const uint32_t sb = smem_u32(smraw);

    const int tid = threadIdx.x;
    const int warp = tid >> 5;
    const int lane = tid & 31;
    const int bm = blockIdx.y * 128;
    const int bn = blockIdx.x * 128;
    const int wm = (warp >> 2) * 64;   // 0,64
    const int wn = (warp & 3) * 32;    // 0,32,64,96

    float acc[4][4][4];
#pragma unroll
    for (int i = 0; i < 4; i++)
#pragma unroll
        for (int j = 0; j < 4; j++)
#pragma unroll
            for (int e = 0; e < 4; e++) acc[i][j][e] = 0.0f;

    const int lrow = lane & 15;
    const int lseg = lane >> 4;

    gemm_issue(sb, 0, 0, A, B, bm, bn, tid);
    gemm_issue(sb, 1, 1, A, B, bm, bn, tid);
    gemm_issue(sb, 2, 2, A, B, bm, bn, tid);

    int stage = 0;
    for (int c = 0; c < NCH; c++) {
        if (c <= NCH - 3) { CP_WAIT(2); }
        else if (c == NCH - 2) { CP_WAIT(1); }
        else { CP_WAIT(0); }
        __syncthreads();

        const uint32_t st = sb + (uint32_t)stage * STAGE_B;
#pragma unroll
        for (int kk = 0; kk < 2; kk++) {
            uint32_t af[4][4];
            uint32_t bf[2][4];
#pragma unroll
            for (int mi = 0; mi < 4; mi++) {
                uint32_t ad = st + OFF_A + (wm + mi * 16 + lrow) * ROWB + kk * 32 + lseg * 16;
                ldsm4(af[mi], ad);
            }
#pragma unroll
            for (int n16 = 0; n16 < 2; n16++) {
                uint32_t ad = st + OFF_B + (wn + n16 * 16 + lrow) * ROWB + kk * 32 + lseg * 16;
                ldsm4(bf[n16], ad);
            }
#pragma unroll
            for (int mi = 0; mi < 4; mi++)
#pragma unroll
                for (int nj = 0; nj < 4; nj++) {
                    const int nh = nj >> 1, sub = nj & 1;
                    mmah(acc[mi][nj], af[mi], bf[nh][sub], bf[nh][sub + 2]);
                }
        }
        __syncthreads();
        if (c + 3 < NCH)
            gemm_issue(sb, stage, c + 3, A, B, bm, bn, tid);
        stage = (stage == 2) ? 0 : stage + 1;
    }

    const int r0 = bm + wm + (lane >> 2);
    const int c0 = bn + wn + (lane & 3) * 2;

    if (EPI == 0) {
#pragma unroll
        for (int mi = 0; mi < 4; mi++)
#pragma unroll
            for (int nj = 0; nj < 4; nj++) {
                const int r = r0 + mi * 16;
                const int cc = c0 + nj * 8;
                float* d0 = Cf + (size_t)r * DMODEL + cc;
                float* d1 = Cf + (size_t)(r + 8) * DMODEL + cc;
                *(float2*)d0 = make_float2(acc[mi][nj][0], acc[mi][nj][1]);
                *(float2*)d1 = make_float2(acc[mi][nj][2], acc[mi][nj][3]);
            }
    } else if (EPI == 1) {
#pragma unroll
        for (int mi = 0; mi < 4; mi++)
#pragma unroll
            for (int nj = 0; nj < 4; nj++) {
                const int r = r0 + mi * 16;
                const int cc = c0 + nj * 8;
                const int h = cc >> 6;
                const int cl = cc & 63;
#pragma unroll
                for (int half = 0; half < 2; half++) {
                    float v0 = acc[mi][nj][half * 2 + 0] * scale;
                    float v1 = acc[mi][nj][half * 2 + 1] * scale;
                    size_t base = ((size_t)(h * T_SEQ + r + half * 8) << 6) + cl;
                    *(uint32_t*)(Ch + base) = packh(v0, v1);
                }
            }
    } else {
        // EPI 2: transpose to [h][d][t] via smem staging (reuse pipeline smem)
        __syncthreads();
        __half* sV = (__half*)smraw;          // [128 n][136 m-pad]
        const int lr0 = wm + (lane >> 2);
        const int lc0 = wn + (lane & 3) * 2;
#pragma unroll
        for (int mi = 0; mi < 4; mi++)
#pragma unroll
            for (int nj = 0; nj < 4; nj++) {
                const int lc = lc0 + nj * 8;
#pragma unroll
                for (int half = 0; half < 2; half++) {
                    int rr = lr0 + mi * 16 + half * 8;
                    sV[lc * 136 + rr] = __float2half_rn(acc[mi][nj][half * 2 + 0]);
                    sV[(lc + 1) * 136 + rr] = __float2half_rn(acc[mi][nj][half * 2 + 1]);
                }
            }
        __syncthreads();
        for (int i = tid; i < 128 * 16; i += 256) {
            int row = i >> 4, seg = i & 15;
            int gn = bn + row;
            int hh = gn >> 6, dd = gn & 63;
            size_t dst = (size_t)(hh * DH + dd) * T_SEQ + bm + seg * 8;
            *(uint4*)(Ch + dst) = *(uint4*)(sV + row * 136 + seg * 8);
        }
    }
}

// ---------------------------------------------------------------------------
// fp16 single-term HMMA sliding-window attention.
// CTA = (64-query tile, head), 4 warps. K [key][d], Vt [d][key], double-buffer.
// ---------------------------------------------------------------------------
#define AROWB 176
#define ATILE (64 * AROWB)                // 11264
#define OFF_K 0
#define OFF_V ATILE
#define ASTAGE (2 * ATILE)                // 22528
#define ATTN_SMEM (2 * ASTAGE)            // 45056

__device__ __forceinline__ void attn_load_tile(
    uint32_t base, const __half* __restrict__ K16, const __half* __restrict__ Vt16,
    int h, int kt, int tid) {
#pragma unroll
    for (int i = 0; i < 4; i++) {
        int idx = tid + i * 128;
        int row = idx >> 3, seg = idx & 7;
        uint32_t off = row * AROWB + seg * 16;
        size_t ks = ((size_t)(h * T_SEQ + kt + row) << 6) + seg * 8;
        cp16(base + OFF_K + off, K16 + ks);
        size_t vs = (size_t)(h * DH + row) * T_SEQ + kt + seg * 8;
        cp16(base + OFF_V + off, Vt16 + vs);
    }
    CP_COMMIT();
}

__global__ void __launch_bounds__(128)
attn_mma(const __half* __restrict__ Q16, const __half* __restrict__ K16,
         const __half* __restrict__ Vt16, __half* __restrict__ AO) {
    extern __shared__ char smraw[];
    const uint32_t sb = smem_u32(smraw);
    const int tid = threadIdx.x;
    const int warp = tid >> 5;
    const int lane = tid & 31;
    const int h = blockIdx.y;
    const int q0 = blockIdx.x * 64;
    const int lrow = lane & 15;
    const int lseg = lane >> 4;

    // stage Q (prescaled) into stage0 K slot
#pragma unroll
    for (int i = 0; i < 4; i++) {
        int idx = tid + i * 128;
        int row = idx >> 3, seg = idx & 7;
        uint32_t dst = sb + OFF_K + row * AROWB + seg * 16;
        size_t qs = ((size_t)(h * T_SEQ + q0 + row) << 6) + seg * 8;
        cp16(dst, Q16 + qs);
    }
    CP_COMMIT();
    CP_WAIT(0);
    __syncthreads();

    uint32_t qf[4][4];
#pragma unroll
    for (int k = 0; k < 4; k++) {
        uint32_t ad = sb + (warp * 16 + lrow) * AROWB + k * 32 + lseg * 16;
        ldsm4(qf[k], ad);
    }
    __syncthreads();

    float o[8][4];
#pragma unroll
    for (int j = 0; j < 8; j++)
#pragma unroll
        for (int e = 0; e < 4; e++) o[j][e] = 0.0f;
    float m0 = -1e30f, m1 = -1e30f, l0 = 0.0f, l1 = 0.0f;

    const int kt_lo = (q0 >= WIN) ? (q0 - WIN) : 0;
    const int ntiles = (q0 - kt_lo) / 64 + 1;

    attn_load_tile(sb, K16, Vt16, h, kt_lo, tid);
    if (ntiles > 1) attn_load_tile(sb + ASTAGE, K16, Vt16, h, kt_lo + 64, tid);

    for (int ti = 0; ti < ntiles; ti++) {
        const int kt = kt_lo + ti * 64;
        const uint32_t base = sb + (uint32_t)(ti & 1) * ASTAGE;
        if (ti + 1 < ntiles) { CP_WAIT(1); } else { CP_WAIT(0); }
        __syncthreads();

        // ---- S = Q K^T ----
        float sf[8][4];
#pragma unroll
        for (int j = 0; j < 8; j++)
#pragma unroll
            for (int e = 0; e < 4; e++) sf[j][e] = 0.0f;
#pragma unroll
        for (int kk = 0; kk < 4; kk++) {
            uint32_t bf[4][4];
#pragma unroll
            for (int n16 = 0; n16 < 4; n16++) {
                uint32_t ad = base + OFF_K + (n16 * 16 + lrow) * AROWB + kk * 32 + lseg * 16;
                ldsm4(bf[n16], ad);
            }
#pragma unroll
            for (int j = 0; j < 8; j++) {
                const int nh = j >> 1, sub = j & 1;
                mmah(sf[j], qf[kk], bf[nh][sub], bf[nh][sub + 2]);
            }
        }

        // ---- mask ----
        const int r0 = q0 + warp * 16 + (lane >> 2);
        const int r1 = r0 + 8;
#pragma unroll
        for (int j = 0; j < 8; j++) {
            const int c0 = kt + 8 * j + (lane & 3) * 2;
            const int c1 = c0 + 1;
            if (c0 > r0 || c0 < r0 - WIN) sf[j][0] = -1e30f;
            if (c1 > r0 || c1 < r0 - WIN) sf[j][1] = -1e30f;
            if (c0 > r1 || c0 < r1 - WIN) sf[j][2] = -1e30f;
            if (c1 > r1 || c1 < r1 - WIN) sf[j][3] = -1e30f;
        }

        // ---- online softmax ----
        float t0 = -1e30f, t1 = -1e30f;
#pragma unroll
        for (int j = 0; j < 8; j++) {
            t0 = fmaxf(t0, fmaxf(sf[j][0], sf[j][1]));
            t1 = fmaxf(t1, fmaxf(sf[j][2], sf[j][3]));
        }
        t0 = fmaxf(t0, __shfl_xor_sync(0xffffffffu, t0, 1));
        t0 = fmaxf(t0, __shfl_xor_sync(0xffffffffu, t0, 2));
        t1 = fmaxf(t1, __shfl_xor_sync(0xffffffffu, t1, 1));
        t1 = fmaxf(t1, __shfl_xor_sync(0xffffffffu, t1, 2));
        const float mn0 = fmaxf(m0, t0), mn1 = fmaxf(m1, t1);
        const float corr0 = __expf(m0 - mn0), corr1 = __expf(m1 - mn1);
        m0 = mn0;
        m1 = mn1;

        uint32_t ph[4][4];
        float s0 = 0.0f, s1 = 0.0f;
#pragma unroll
        for (int j = 0; j < 8; j++) {
            float p0 = __expf(sf[j][0] - m0);
            float p1 = __expf(sf[j][1] - m0);
            float p2 = __expf(sf[j][2] - m1);
            float p3 = __expf(sf[j][3] - m1);
            s0 += p0 + p1;
            s1 += p2 + p3;
            const int kk = j >> 1, pos = (j & 1) * 2;
            ph[kk][pos + 0] = packh(p0, p1);
            ph[kk][pos + 1] = packh(p2, p3);
        }
        s0 += __shfl_xor_sync(0xffffffffu, s0, 1);
        s0 += __shfl_xor_sync(0xffffffffu, s0, 2);
        s1 += __shfl_xor_sync(0xffffffffu, s1, 1);
        s1 += __shfl_xor_sync(0xffffffffu, s1, 2);
        l0 = l0 * corr0 + s0;
        l1 = l1 * corr1 + s1;
#pragma unroll
        for (int j = 0; j < 8; j++) {
            o[j][0] *= corr0;
            o[j][1] *= corr0;
            o[j][2] *= corr1;
            o[j][3] *= corr1;
        }

        // ---- O += P V ----
#pragma unroll
        for (int kk = 0; kk < 4; kk++) {
            uint32_t vf[4][4];
#pragma unroll
            for (int n16 = 0; n16 < 4; n16++) {
                uint32_t ad = base + OFF_V + (n16 * 16 + lrow) * AROWB + kk * 32 + lseg * 16;
                ldsm4(vf[n16], ad);
            }
#pragma unroll
            for (int j = 0; j < 8; j++) {
                const int nh = j >> 1, sub = j & 1;
                mmah(o[j], ph[kk], vf[nh][sub], vf[nh][sub + 2]);
            }
        }
        __syncthreads();
        if (ti + 2 < ntiles)
            attn_load_tile(sb + (uint32_t)(ti & 1) * ASTAGE, K16, Vt16, h, kt + 128, tid);
    }

    // ---- epilogue: O/l -> fp16 AO [t][h*64+d] ----
    const float i0 = 1.0f / l0;
    const float i1 = 1.0f / l1;
    const int tr = q0 + warp * 16 + (lane >> 2);
#pragma unroll
    for (int j = 0; j < 8; j++) {
        const int d = 8 * j + (lane & 3) * 2;
        size_t a0 = (size_t)tr * DMODEL + h * DH + d;
        size_t a1 = (size_t)(tr + 8) * DMODEL + h * DH + d;
        *(uint32_t*)(AO + a0) = packh(o[j][0] * i0, o[j][1] * i0);
        *(uint32_t*)(AO + a1) = packh(o[j][2] * i1, o[j][3] * i1);
    }
}

// ---------------------------------------------------------------------------
extern "C" void kernel_launch(void* const* d_in, const int* in_sizes, int n_in,
                              void* d_out, int out_size) {
    const float* x  = (const float*)d_in[0];
    const float* Wq = (const float*)d_in[1];
    const float* Wk = (const float*)d_in[2];
    const float* Wv = (const float*)d_in[3];
    const float* Wo = (const float*)d_in[4];
    float* out = (float*)d_out;

    __half *px16, *pW16, *pao16, *pQ16, *pK16, *pVt16;
    cudaGetSymbolAddress((void**)&px16, g_x16);
    cudaGetSymbolAddress((void**)&pW16, g_W16);
    cudaGetSymbolAddress((void**)&pao16, g_ao16);
    cudaGetSymbolAddress((void**)&pQ16, g_Q16);
    cudaGetSymbolAddress((void**)&pK16, g_K16);
    cudaGetSymbolAddress((void**)&pVt16, g_Vt16);

    cudaFuncSetAttribute(gemm_mma<0>, cudaFuncAttributeMaxDynamicSharedMemorySize, GEMM_SMEM);
    cudaFuncSetAttribute(gemm_mma<1>, cudaFuncAttributeMaxDynamicSharedMemorySize, GEMM_SMEM);
    cudaFuncSetAttribute(gemm_mma<2>, cudaFuncAttributeMaxDynamicSharedMemorySize, GEMM_SMEM);
    cudaFuncSetAttribute(attn_mma, cudaFuncAttributeMaxDynamicSharedMemorySize, ATTN_SMEM);

    const int n4x = T_SEQ * DMODEL / 4;
    const int n4w = DMODEL * DMODEL / 4;
    const int WSZ = DMODEL * DMODEL;

    convX<<<n4x / 256, 256>>>(x, px16, n4x);
    dim3 wgrid(n4w / 256, 4);
    convW<<<wgrid, 256>>>(Wq, Wk, Wv, Wo, pW16);

    dim3 ggrid(DMODEL / 128, T_SEQ / 128);  // (8, 32) = 256 CTAs, 2/SM resident
    gemm_mma<1><<<ggrid, 256, GEMM_SMEM>>>(px16, pW16 + 0 * WSZ, nullptr, pQ16, 0.125f);
    gemm_mma<1><<<ggrid, 256, GEMM_SMEM>>>(px16, pW16 + 1 * WSZ, nullptr, pK16, 1.0f);
    gemm_mma<2><<<ggrid, 256, GEMM_SMEM>>>(px16, pW16 + 2 * WSZ, nullptr, pVt16, 1.0f);

    dim3 agrid(T_SEQ / 64, NHEADS);  // (64, 16)
    attn_mma<<<agrid, 128, ATTN_SMEM>>>(pQ16, pK16, pVt16, pao16);

    gemm_mma<0><<<ggrid, 256, GEMM_SMEM>>>(pao16, pW16 + 3 * WSZ, out, nullptr, 1.0f);
}

// round 9
// speedup vs baseline: 6.0082x; 1.0587x over previous
#include <cuda_runtime.h>
#include <cuda_fp16.h>
#include <cstdint>
#include <math.h>

#define T_SEQ 4096
#define DMODEL 1024
#define NHEADS 16
#define DH 64
#define WIN 256

// ---------------------------------------------------------------------------
// Scratch (__device__ globals; allocation-free rule). All fp16, single copy.
// ---------------------------------------------------------------------------
__device__ __align__(16) __half g_x16[T_SEQ * DMODEL];
__device__ __align__(16) __half g_W16[4 * DMODEL * DMODEL];
__device__ __align__(16) __half g_ao16[T_SEQ * DMODEL];
__device__ __align__(16) __half g_Q16[NHEADS * T_SEQ * DH];   // [h][t][d], prescaled
__device__ __align__(16) __half g_K16[NHEADS * T_SEQ * DH];   // [h][t][d]
__device__ __align__(16) __half g_Vt16[NHEADS * DH * T_SEQ];  // [h][d][t]

// ---------------------------------------------------------------------------
// PTX helpers (generic PTX only)
// ---------------------------------------------------------------------------
__device__ __forceinline__ uint32_t smem_u32(const void* p) {
    uint32_t a;
    asm("{ .reg .u64 t; cvta.to.shared.u64 t, %1; cvt.u32.u64 %0, t; }"
        : "=r"(a) : "l"(p));
    return a;
}

__device__ __forceinline__ void cp16(uint32_t dst, const void* src) {
    asm volatile("cp.async.cg.shared.global [%0], [%1], 16;" :: "r"(dst), "l"(src));
}
#define CP_COMMIT() asm volatile("cp.async.commit_group;" ::: "memory")
#define CP_WAIT(n)  asm volatile("cp.async.wait_group %0;" :: "n"(n) : "memory")

__device__ __forceinline__ void ldsm4(uint32_t (&r)[4], uint32_t addr) {
    asm volatile("ldmatrix.sync.aligned.m8n8.x4.shared.b16 {%0,%1,%2,%3}, [%4];"
                 : "=r"(r[0]), "=r"(r[1]), "=r"(r[2]), "=r"(r[3]) : "r"(addr));
}

__device__ __forceinline__ void mmah(float (&d)[4], const uint32_t (&a)[4],
                                     uint32_t b0, uint32_t b1) {
    asm volatile(
        "mma.sync.aligned.m16n8k16.row.col.f32.f16.f16.f32 "
        "{%0,%1,%2,%3}, {%4,%5,%6,%7}, {%8,%9}, {%0,%1,%2,%3};"
        : "+f"(d[0]), "+f"(d[1]), "+f"(d[2]), "+f"(d[3])
        : "r"(a[0]), "r"(a[1]), "r"(a[2]), "r"(a[3]), "r"(b0), "r"(b1));
}

__device__ __forceinline__ uint32_t packh(float x, float y) {
    __half hx = __float2half_rn(x), hy = __float2half_rn(y);
    return (uint32_t)__half_as_ushort(hx) | ((uint32_t)__half_as_ushort(hy) << 16);
}

// ---------------------------------------------------------------------------
// fp32 -> fp16 conversions
// ---------------------------------------------------------------------------
__global__ void convX(const float* __restrict__ in, __half* __restrict__ out, int n4) {
    int i = blockIdx.x * 256 + threadIdx.x;
    if (i >= n4) return;
    float4 v = ((const float4*)in)[i];
    uint2 o;
    o.x = packh(v.x, v.y);
    o.y = packh(v.z, v.w);
    ((uint2*)out)[i] = o;
}

__global__ void convW(const float* __restrict__ W0, const float* __restrict__ W1,
                      const float* __restrict__ W2, const float* __restrict__ W3,
                      __half* __restrict__ out) {
    const int w = blockIdx.y;
    const float* src = (w == 0) ? W0 : (w == 1) ? W1 : (w == 2) ? W2 : W3;
    const int WSZ = DMODEL * DMODEL;
    int i = blockIdx.x * 256 + threadIdx.x;
    float4 v = ((const float4*)src)[i];
    uint2 o;
    o.x = packh(v.x, v.y);
    o.y = packh(v.z, v.w);
    ((uint2*)(out + (size_t)w * WSZ))[i] = o;
}

// ---------------------------------------------------------------------------
// fp16 GEMM machinery: C[m,n] = sum_k A[m,k]*B[n,k]
// CTA 128x128, 256 thr / 8 warps (warp tile 64x32), KC=32.
// 4-stage cp.async pipeline, ONE sync per chunk (issue c+3 hits stage (c-1)&3,
// which the iteration-c barrier already protects). 2 CTAs/SM.
// ---------------------------------------------------------------------------
#define KC 32
#define ROWB 80
#define TILE_B (128 * ROWB)              // 10240
#define OFF_A 0
#define OFF_B TILE_B
#define STAGE_B (2 * TILE_B)             // 20480
#define NSTAGE 4
#define GEMM_SMEM (NSTAGE * STAGE_B)     // 81920
#define NCH (DMODEL / KC)                // 32

__device__ __forceinline__ void gemm_issue(
    uint32_t sb, int stage, int chunk,
    const __half* __restrict__ A, const __half* __restrict__ B,
    int bm, int bn, int tid) {
    const uint32_t st = sb + (uint32_t)stage * STAGE_B;
    const __half* aA = A + (size_t)bm * DMODEL;
    const __half* bB = B + (size_t)bn * DMODEL;
#pragma unroll
    for (int i = 0; i < 2; i++) {
        int slot = tid + i * 256;
        int row = slot >> 2, seg = slot & 3;
        uint32_t off = row * ROWB + seg * 16;
        const size_t g = (size_t)row * DMODEL + chunk * KC + seg * 8;
        cp16(st + OFF_A + off, aA + g);
        cp16(st + OFF_B + off, bB + g);
    }
    CP_COMMIT();
}

__device__ __forceinline__ void gemm_main(
    uint32_t sb, const __half* __restrict__ A, const __half* __restrict__ B,
    int bm, int bn, int tid, int wm, int wn, int lrow, int lseg,
    float (&acc)[4][4][4]) {
#pragma unroll
    for (int i = 0; i < 4; i++)
#pragma unroll
        for (int j = 0; j < 4; j++)
#pragma unroll
            for (int e = 0; e < 4; e++) acc[i][j][e] = 0.0f;

    gemm_issue(sb, 0, 0, A, B, bm, bn, tid);
    gemm_issue(sb, 1, 1, A, B, bm, bn, tid);
    gemm_issue(sb, 2, 2, A, B, bm, bn, tid);

    for (int c = 0; c < NCH; c++) {
        if (c <= NCH - 3) { CP_WAIT(2); }
        else if (c == NCH - 2) { CP_WAIT(1); }
        else { CP_WAIT(0); }
        __syncthreads();

        // prefetch chunk c+3 into stage (c+3)&3 == (c-1)&3 (safe: barrier above
        // guarantees all warps finished computing on that stage at iter c-1)
        if (c + 3 < NCH)
            gemm_issue(sb, (c + 3) & 3, c + 3, A, B, bm, bn, tid);

        const uint32_t st = sb + (uint32_t)(c & 3) * STAGE_B;
#pragma unroll
        for (int kk = 0; kk < 2; kk++) {
            uint32_t af[4][4];
            uint32_t bf[2][4];
#pragma unroll
            for (int mi = 0; mi < 4; mi++) {
                uint32_t ad = st + OFF_A + (wm + mi * 16 + lrow) * ROWB + kk * 32 + lseg * 16;
                ldsm4(af[mi], ad);
            }
#pragma unroll
            for (int n16 = 0; n16 < 2; n16++) {
                uint32_t ad = st + OFF_B + (wn + n16 * 16 + lrow) * ROWB + kk * 32 + lseg * 16;
                ldsm4(bf[n16], ad);
            }
#pragma unroll
            for (int mi = 0; mi < 4; mi++)
#pragma unroll
                for (int nj = 0; nj < 4; nj++) {
                    const int nh = nj >> 1, sub = nj & 1;
                    mmah(acc[mi][nj], af[mi], bf[nh][sub], bf[nh][sub + 2]);
                }
        }
    }
}

// head-major epilogue: fp16 [h][t][d] * scale
__device__ __forceinline__ void epi_head(
    const float (&acc)[4][4][4], __half* __restrict__ Ch, float scale,
    int r0, int c0) {
#pragma unroll
    for (int mi = 0; mi < 4; mi++)
#pragma unroll
        for (int nj = 0; nj < 4; nj++) {
            const int r = r0 + mi * 16;
            const int cc = c0 + nj * 8;
            const int h = cc >> 6;
            const int cl = cc & 63;
#pragma unroll
            for (int half = 0; half < 2; half++) {
                float v0 = acc[mi][nj][half * 2 + 0] * scale;
                float v1 = acc[mi][nj][half * 2 + 1] * scale;
                size_t base = ((size_t)(h * T_SEQ + r + half * 8) << 6) + cl;
                *(uint32_t*)(Ch + base) = packh(v0, v1);
            }
        }
}

// fused Q/K/V projection: blockIdx.z selects weight + epilogue
__global__ void __launch_bounds__(256, 2)
gemm_qkv(const __half* __restrict__ A, const __half* __restrict__ W,
         __half* __restrict__ Q, __half* __restrict__ K, __half* __restrict__ Vt) {
    extern __shared__ char smraw[];
    const uint32_t sb = smem_u32(smraw);

    const int tid = threadIdx.x;
    const int warp = tid >> 5;
    const int lane = tid & 31;
    const int bm = blockIdx.y * 128;
    const int bn = blockIdx.x * 128;
    const int z = blockIdx.z;
    const int wm = (warp >> 2) * 64;
    const int wn = (warp & 3) * 32;
    const int lrow = lane & 15;
    const int lseg = lane >> 4;

    const __half* B = W + (size_t)z * DMODEL * DMODEL;

    float acc[4][4][4];
    gemm_main(sb, A, B, bm, bn, tid, wm, wn, lrow, lseg, acc);

    const int r0 = bm + wm + (lane >> 2);
    const int c0 = bn + wn + (lane & 3) * 2;

    if (z == 0) {
        epi_head(acc, Q, 0.125f, r0, c0);
    } else if (z == 1) {
        epi_head(acc, K, 1.0f, r0, c0);
    } else {
        // V: transpose to [h][d][t] via smem staging (reuse pipeline smem)
        __syncthreads();
        __half* sV = (__half*)smraw;          // [128 n][136 m-pad]
        const int lr0 = wm + (lane >> 2);
        const int lc0 = wn + (lane & 3) * 2;
#pragma unroll
        for (int mi = 0; mi < 4; mi++)
#pragma unroll
            for (int nj = 0; nj < 4; nj++) {
                const int lc = lc0 + nj * 8;
#pragma unroll
                for (int half = 0; half < 2; half++) {
                    int rr = lr0 + mi * 16 + half * 8;
                    sV[lc * 136 + rr] = __float2half_rn(acc[mi][nj][half * 2 + 0]);
                    sV[(lc + 1) * 136 + rr] = __float2half_rn(acc[mi][nj][half * 2 + 1]);
                }
            }
        __syncthreads();
        for (int i = tid; i < 128 * 16; i += 256) {
            int row = i >> 4, seg = i & 15;
            int gn = bn + row;
            int hh = gn >> 6, dd = gn & 63;
            size_t dst = (size_t)(hh * DH + dd) * T_SEQ + bm + seg * 8;
            *(uint4*)(Vt + dst) = *(uint4*)(sV + row * 136 + seg * 8);
        }
    }
}

// output projection: fp32 row-major
__global__ void __launch_bounds__(256, 2)
gemm_out(const __half* __restrict__ A, const __half* __restrict__ B,
         float* __restrict__ Cf) {
    extern __shared__ char smraw[];
    const uint32_t sb = smem_u32(smraw);

    const int tid = threadIdx.x;
    const int warp = tid >> 5;
    const int lane = tid & 31;
    const int bm = blockIdx.y * 128;
    const int bn = blockIdx.x * 128;
    const int wm = (warp >> 2) * 64;
    const int wn = (warp & 3) * 32;
    const int lrow = lane & 15;
    const int lseg = lane >> 4;

    float acc[4][4][4];
    gemm_main(sb, A, B, bm, bn, tid, wm, wn, lrow, lseg, acc);

    const int r0 = bm + wm + (lane >> 2);
    const int c0 = bn + wn + (lane & 3) * 2;
#pragma unroll
    for (int mi = 0; mi < 4; mi++)
#pragma unroll
        for (int nj = 0; nj < 4; nj++) {
            const int r = r0 + mi * 16;
            const int cc = c0 + nj * 8;
            float* d0 = Cf + (size_t)r * DMODEL + cc;
            float* d1 = Cf + (size_t)(r + 8) * DMODEL + cc;
            *(float2*)d0 = make_float2(acc[mi][nj][0], acc[mi][nj][1]);
            *(float2*)d1 = make_float2(acc[mi][nj][2], acc[mi][nj][3]);
        }
}

// ---------------------------------------------------------------------------
// fp16 single-term HMMA sliding-window attention (unchanged from R8).
// ---------------------------------------------------------------------------
#define AROWB 176
#define ATILE (64 * AROWB)                // 11264
#define OFF_K 0
#define OFF_V ATILE
#define ASTAGE (2 * ATILE)                // 22528
#define ATTN_SMEM (2 * ASTAGE)            // 45056

__device__ __forceinline__ void attn_load_tile(
    uint32_t base, const __half* __restrict__ K16, const __half* __restrict__ Vt16,
    int h, int kt, int tid) {
#pragma unroll
    for (int i = 0; i < 4; i++) {
        int idx = tid + i * 128;
        int row = idx >> 3, seg = idx & 7;
        uint32_t off = row * AROWB + seg * 16;
        size_t ks = ((size_t)(h * T_SEQ + kt + row) << 6) + seg * 8;
        cp16(base + OFF_K + off, K16 + ks);
        size_t vs = (size_t)(h * DH + row) * T_SEQ + kt + seg * 8;
        cp16(base + OFF_V + off, Vt16 + vs);
    }
    CP_COMMIT();
}

__global__ void __launch_bounds__(128)
attn_mma(const __half* __restrict__ Q16, const __half* __restrict__ K16,
         const __half* __restrict__ Vt16, __half* __restrict__ AO) {
    extern __shared__ char smraw[];
    const uint32_t sb = smem_u32(smraw);
    const int tid = threadIdx.x;
    const int warp = tid >> 5;
    const int lane = tid & 31;
    const int h = blockIdx.y;
    const int q0 = blockIdx.x * 64;
    const int lrow = lane & 15;
    const int lseg = lane >> 4;

#pragma unroll
    for (int i = 0; i < 4; i++) {
        int idx = tid + i * 128;
        int row = idx >> 3, seg = idx & 7;
        uint32_t dst = sb + OFF_K + row * AROWB + seg * 16;
        size_t qs = ((size_t)(h * T_SEQ + q0 + row) << 6) + seg * 8;
        cp16(dst, Q16 + qs);
    }
    CP_COMMIT();
    CP_WAIT(0);
    __syncthreads();

    uint32_t qf[4][4];
#pragma unroll
    for (int k = 0; k < 4; k++) {
        uint32_t ad = sb + (warp * 16 + lrow) * AROWB + k * 32 + lseg * 16;
        ldsm4(qf[k], ad);
    }
    __syncthreads();

    float o[8][4];
#pragma unroll
    for (int j = 0; j < 8; j++)
#pragma unroll
        for (int e = 0; e < 4; e++) o[j][e] = 0.0f;
    float m0 = -1e30f, m1 = -1e30f, l0 = 0.0f, l1 = 0.0f;

    const int kt_lo = (q0 >= WIN) ? (q0 - WIN) : 0;
    const int ntiles = (q0 - kt_lo) / 64 + 1;

    attn_load_tile(sb, K16, Vt16, h, kt_lo, tid);
    if (ntiles > 1) attn_load_tile(sb + ASTAGE, K16, Vt16, h, kt_lo + 64, tid);

    for (int ti = 0; ti < ntiles; ti++) {
        const int kt = kt_lo + ti * 64;
        const uint32_t base = sb + (uint32_t)(ti & 1) * ASTAGE;
        if (ti + 1 < ntiles) { CP_WAIT(1); } else { CP_WAIT(0); }
        __syncthreads();

        float sf[8][4];
#pragma unroll
        for (int j = 0; j < 8; j++)
#pragma unroll
            for (int e = 0; e < 4; e++) sf[j][e] = 0.0f;
#pragma unroll
        for (int kk = 0; kk < 4; kk++) {
            uint32_t bf[4][4];
#pragma unroll
            for (int n16 = 0; n16 < 4; n16++) {
                uint32_t ad = base + OFF_K + (n16 * 16 + lrow) * AROWB + kk * 32 + lseg * 16;
                ldsm4(bf[n16], ad);
            }
#pragma unroll
            for (int j = 0; j < 8; j++) {
                const int nh = j >> 1, sub = j & 1;
                mmah(sf[j], qf[kk], bf[nh][sub], bf[nh][sub + 2]);
            }
        }

        const int r0 = q0 + warp * 16 + (lane >> 2);
        const int r1 = r0 + 8;
#pragma unroll
        for (int j = 0; j < 8; j++) {
            const int c0 = kt + 8 * j + (lane & 3) * 2;
            const int c1 = c0 + 1;
            if (c0 > r0 || c0 < r0 - WIN) sf[j][0] = -1e30f;
            if (c1 > r0 || c1 < r0 - WIN) sf[j][1] = -1e30f;
            if (c0 > r1 || c0 < r1 - WIN) sf[j][2] = -1e30f;
            if (c1 > r1 || c1 < r1 - WIN) sf[j][3] = -1e30f;
        }

        float t0 = -1e30f, t1 = -1e30f;
#pragma unroll
        for (int j = 0; j < 8; j++) {
            t0 = fmaxf(t0, fmaxf(sf[j][0], sf[j][1]));
            t1 = fmaxf(t1, fmaxf(sf[j][2], sf[j][3]));
        }
        t0 = fmaxf(t0, __shfl_xor_sync(0xffffffffu, t0, 1));
        t0 = fmaxf(t0, __shfl_xor_sync(0xffffffffu, t0, 2));
        t1 = fmaxf(t1, __shfl_xor_sync(0xffffffffu, t1, 1));
        t1 = fmaxf(t1, __shfl_xor_sync(0xffffffffu, t1, 2));
        const float mn0 = fmaxf(m0, t0), mn1 = fmaxf(m1, t1);
        const float corr0 = __expf(m0 - mn0), corr1 = __expf(m1 - mn1);
        m0 = mn0;
        m1 = mn1;

        uint32_t ph[4][4];
        float s0 = 0.0f, s1 = 0.0f;
#pragma unroll
        for (int j = 0; j < 8; j++) {
            float p0 = __expf(sf[j][0] - m0);
            float p1 = __expf(sf[j][1] - m0);
            float p2 = __expf(sf[j][2] - m1);
            float p3 = __expf(sf[j][3] - m1);
            s0 += p0 + p1;
            s1 += p2 + p3;
            const int kk = j >> 1, pos = (j & 1) * 2;
            ph[kk][pos + 0] = packh(p0, p1);
            ph[kk][pos + 1] = packh(p2, p3);
        }
        s0 += __shfl_xor_sync(0xffffffffu, s0, 1);
        s0 += __shfl_xor_sync(0xffffffffu, s0, 2);
        s1 += __shfl_xor_sync(0xffffffffu, s1, 1);
        s1 += __shfl_xor_sync(0xffffffffu, s1, 2);
        l0 = l0 * corr0 + s0;
        l1 = l1 * corr1 + s1;
#pragma unroll
        for (int j = 0; j < 8; j++) {
            o[j][0] *= corr0;
            o[j][1] *= corr0;
            o[j][2] *= corr1;
            o[j][3] *= corr1;
        }

#pragma unroll
        for (int kk = 0; kk < 4; kk++) {
            uint32_t vf[4][4];
#pragma unroll
            for (int n16 = 0; n16 < 4; n16++) {
                uint32_t ad = base + OFF_V + (n16 * 16 + lrow) * AROWB + kk * 32 + lseg * 16;
                ldsm4(vf[n16], ad);
            }
#pragma unroll
            for (int j = 0; j < 8; j++) {
                const int nh = j >> 1, sub = j & 1;
                mmah(o[j], ph[kk], vf[nh][sub], vf[nh][sub + 2]);
            }
        }
        __syncthreads();
        if (ti + 2 < ntiles)
            attn_load_tile(sb + (uint32_t)(ti & 1) * ASTAGE, K16, Vt16, h, kt + 128, tid);
    }

    const float i0 = 1.0f / l0;
    const float i1 = 1.0f / l1;
    const int tr = q0 + warp * 16 + (lane >> 2);
#pragma unroll
    for (int j = 0; j < 8; j++) {
        const int d = 8 * j + (lane & 3) * 2;
        size_t a0 = (size_t)tr * DMODEL + h * DH + d;
        size_t a1 = (size_t)(tr + 8) * DMODEL + h * DH + d;
        *(uint32_t*)(AO + a0) = packh(o[j][0] * i0, o[j][1] * i0);
        *(uint32_t*)(AO + a1) = packh(o[j][2] * i1, o[j][3] * i1);
    }
}

// ---------------------------------------------------------------------------
extern "C" void kernel_launch(void* const* d_in, const int* in_sizes, int n_in,
                              void* d_out, int out_size) {
    const float* x  = (const float*)d_in[0];
    const float* Wq = (const float*)d_in[1];
    const float* Wk = (const float*)d_in[2];
    const float* Wv = (const float*)d_in[3];
    const float* Wo = (const float*)d_in[4];
    float* out = (float*)d_out;

    __half *px16, *pW16, *pao16, *pQ16, *pK16, *pVt16;
    cudaGetSymbolAddress((void**)&px16, g_x16);
    cudaGetSymbolAddress((void**)&pW16, g_W16);
    cudaGetSymbolAddress((void**)&pao16, g_ao16);
    cudaGetSymbolAddress((void**)&pQ16, g_Q16);
    cudaGetSymbolAddress((void**)&pK16, g_K16);
    cudaGetSymbolAddress((void**)&pVt16, g_Vt16);

    cudaFuncSetAttribute(gemm_qkv, cudaFuncAttributeMaxDynamicSharedMemorySize, GEMM_SMEM);
    cudaFuncSetAttribute(gemm_out, cudaFuncAttributeMaxDynamicSharedMemorySize, GEMM_SMEM);
    cudaFuncSetAttribute(attn_mma, cudaFuncAttributeMaxDynamicSharedMemorySize, ATTN_SMEM);

    const int n4x = T_SEQ * DMODEL / 4;
    const int n4w = DMODEL * DMODEL / 4;
    const int WSZ = DMODEL * DMODEL;

    convX<<<n4x / 256, 256>>>(x, px16, n4x);
    dim3 wgrid(n4w / 256, 4);
    convW<<<wgrid, 256>>>(Wq, Wk, Wv, Wo, pW16);

    dim3 qkvgrid(DMODEL / 128, T_SEQ / 128, 3);  // (8, 32, 3) = 768 CTAs
    gemm_qkv<<<qkvgrid, 256, GEMM_SMEM>>>(px16, pW16, pQ16, pK16, pVt16);

    dim3 agrid(T_SEQ / 64, NHEADS);  // (64, 16)
    attn_mma<<<agrid, 128, ATTN_SMEM>>>(pQ16, pK16, pVt16, pao16);

    dim3 ogrid(DMODEL / 128, T_SEQ / 128);
    gemm_out<<<ogrid, 256, GEMM_SMEM>>>(pao16, pW16 + 3 * WSZ, out);
}